// round 4
// baseline (speedup 1.0000x reference)
#include <cuda_runtime.h>
#include <cuda_bf16.h>
#include <cstdint>
#include <math.h>

#define HH 256
#define WW 256
#define DD 64
#define NH 8
#define INNER 512
#define KBIG 16384

__device__ float g_QH[NH * WW * HH * 64];
__device__ float g_KH[NH * WW * HH * 64];
__device__ float g_VH[HH * WW * INNER];
__device__ float g_DOTS[NH * WW * WW];
__device__ float g_PB[NH * WW * WW];

// ---------------- warp-MMA helpers (sm_80+ baseline; no tcgen05) -------------
__device__ __forceinline__ void ldsm4(uint32_t* r, uint32_t a) {
    asm volatile("ldmatrix.sync.aligned.m8n8.x4.shared.b16 {%0,%1,%2,%3}, [%4];"
                 : "=r"(r[0]), "=r"(r[1]), "=r"(r[2]), "=r"(r[3]) : "r"(a));
}
__device__ __forceinline__ void ldsm4t(uint32_t* r, uint32_t a) {
    asm volatile("ldmatrix.sync.aligned.m8n8.x4.trans.shared.b16 {%0,%1,%2,%3}, [%4];"
                 : "=r"(r[0]), "=r"(r[1]), "=r"(r[2]), "=r"(r[3]) : "r"(a));
}
__device__ __forceinline__ void mma16816(float* c, const uint32_t* a, const uint32_t* b) {
    asm volatile("mma.sync.aligned.m16n8k16.row.col.f32.bf16.bf16.f32 "
                 "{%0,%1,%2,%3},{%4,%5,%6,%7},{%8,%9},{%0,%1,%2,%3};"
                 : "+f"(c[0]), "+f"(c[1]), "+f"(c[2]), "+f"(c[3])
                 : "r"(a[0]), "r"(a[1]), "r"(a[2]), "r"(a[3]), "r"(b[0]), "r"(b[1]));
}
__device__ __forceinline__ void split2(float a, float b, uint32_t& h, uint32_t& l) {
    __nv_bfloat162 hv = __floats2bfloat162_rn(a, b);
    float2 hf = __bfloat1622float2(hv);
    __nv_bfloat162 lv = __floats2bfloat162_rn(a - hf.x, b - hf.y);
    h = *reinterpret_cast<uint32_t*>(&hv);
    l = *reinterpret_cast<uint32_t*>(&lv);
}

#define XS 72  // bf16 row stride (144B: 16B-aligned rows, low ldsm conflicts)

// ============================================================================
// Width attention via mma.sync bf16 split-3. Block = (column w, head). 8 warps.
// smem: X/V(hi,lo) 256xXS, K(hi,lo) 256xXS, W(hi,lo) 64xXS  = 165,888 B
// ============================================================================
__global__ void __launch_bounds__(256, 1)
k_width_mma(const float* __restrict__ x, const float* __restrict__ Wq,
            const float* __restrict__ Wkv, const float* __restrict__ Wout,
            float* __restrict__ out) {
    extern __shared__ __nv_bfloat16 sb[];
    __nv_bfloat16* Xh = sb;                 // later: V hi
    __nv_bfloat16* Xl = sb + 256 * XS;      // later: V lo
    __nv_bfloat16* Kh = sb + 2 * 256 * XS;
    __nv_bfloat16* Kl = sb + 3 * 256 * XS;
    __nv_bfloat16* Wh = sb + 4 * 256 * XS;
    __nv_bfloat16* Wl = Wh + 64 * XS;

    const int t = threadIdx.x, lane = t & 31, warp = t >> 5, m0 = warp * 32;
    const int w = blockIdx.x, head = blockIdx.y;

    // ---- X column w -> bf16 hi/lo (row t) ----
    {
        const float4* src = (const float4*)(x + (size_t)t * (WW * DD) + w * DD);
#pragma unroll
        for (int q4 = 0; q4 < 16; q4++) {
            float4 v = src[q4];
            uint32_t h0, l0, h1, l1;
            split2(v.x, v.y, h0, l0);
            split2(v.z, v.w, h1, l1);
            *(uint32_t*)(Xh + t * XS + q4 * 4) = h0;
            *(uint32_t*)(Xh + t * XS + q4 * 4 + 2) = h1;
            *(uint32_t*)(Xl + t * XS + q4 * 4) = l0;
            *(uint32_t*)(Xl + t * XS + q4 * 4 + 2) = l1;
        }
    }
    auto loadW = [&](const float* wsrc, int stride, float scale) {
        for (int e = t; e < 2048; e += 256) {
            int k = e >> 5, n2 = e & 31;
            float2 v = *(const float2*)(wsrc + (size_t)k * stride + n2 * 2);
            uint32_t h, l;
            split2(v.x * scale, v.y * scale, h, l);
            *(uint32_t*)(Wh + k * XS + n2 * 2) = h;
            *(uint32_t*)(Wl + k * XS + n2 * 2) = l;
        }
    };
    // ldmatrix address builders
    auto aAddr = [&](const __nv_bfloat16* base, int r0, int k0) -> uint32_t {
        int row = r0 + (lane & 15), col = k0 + ((lane >> 4) << 3);
        return (uint32_t)__cvta_generic_to_shared(base + row * XS + col);
    };
    auto bAddrT = [&](const __nv_bfloat16* base, int k0, int n0) -> uint32_t {  // W, V
        int row = k0 + (lane & 7) + (((lane >> 3) & 1) << 3);
        int col = n0 + ((lane >> 4) << 3);
        return (uint32_t)__cvta_generic_to_shared(base + row * XS + col);
    };
    auto bAddrN = [&](const __nv_bfloat16* base, int j0, int d0) -> uint32_t {  // K^T
        int row = j0 + (lane & 7) + ((lane >> 4) << 3);
        int col = d0 + (((lane >> 3) & 1) << 3);
        return (uint32_t)__cvta_generic_to_shared(base + row * XS + col);
    };
    // C[32x64] = X[own rows] @ Wsm, 3-term split
    auto proj = [&](float (&c)[2][8][4]) {
#pragma unroll
        for (int mi = 0; mi < 2; mi++)
#pragma unroll
            for (int nt = 0; nt < 8; nt++)
#pragma unroll
                for (int i = 0; i < 4; i++) c[mi][nt][i] = 0.f;
#pragma unroll
        for (int ks = 0; ks < 4; ks++) {
            uint32_t ah[2][4], al[2][4];
            ldsm4(ah[0], aAddr(Xh, m0, ks * 16));
            ldsm4(ah[1], aAddr(Xh, m0 + 16, ks * 16));
            ldsm4(al[0], aAddr(Xl, m0, ks * 16));
            ldsm4(al[1], aAddr(Xl, m0 + 16, ks * 16));
#pragma unroll
            for (int np = 0; np < 4; np++) {
                uint32_t bh[4], bl[4];
                ldsm4t(bh, bAddrT(Wh, ks * 16, np * 16));
                ldsm4t(bl, bAddrT(Wl, ks * 16, np * 16));
#pragma unroll
                for (int mi = 0; mi < 2; mi++)
#pragma unroll
                    for (int hf = 0; hf < 2; hf++) {
                        float* cc = c[mi][np * 2 + hf];
                        mma16816(cc, ah[mi], bh + hf * 2);
                        mma16816(cc, al[mi], bh + hf * 2);
                        mma16816(cc, ah[mi], bl + hf * 2);
                    }
            }
        }
    };
    auto storeC = [&](float (&c)[2][8][4], __nv_bfloat16* Dh, __nv_bfloat16* Dl) {
#pragma unroll
        for (int mi = 0; mi < 2; mi++)
#pragma unroll
            for (int nt = 0; nt < 8; nt++) {
                int r = m0 + mi * 16 + (lane >> 2), cc = nt * 8 + ((lane & 3) << 1);
                uint32_t h, l;
                split2(c[mi][nt][0], c[mi][nt][1], h, l);
                *(uint32_t*)(Dh + r * XS + cc) = h;
                *(uint32_t*)(Dl + r * XS + cc) = l;
                split2(c[mi][nt][2], c[mi][nt][3], h, l);
                *(uint32_t*)(Dh + (r + 8) * XS + cc) = h;
                *(uint32_t*)(Dl + (r + 8) * XS + cc) = l;
            }
    };

    float c[2][8][4];
    loadW(Wkv + head * 64, 1024, 1.f);  // Wk
    __syncthreads();
    proj(c);
    storeC(c, Kh, Kl);
    __syncthreads();
    loadW(Wq + head * 64, 512, 0.125f);  // Wq (scale folded)
    __syncthreads();
    proj(c);
    // Q -> register A-fragments (hi/lo)
    uint32_t qh[2][4][4], ql[2][4][4];
#pragma unroll
    for (int mi = 0; mi < 2; mi++)
#pragma unroll
        for (int ks = 0; ks < 4; ks++) {
            split2(c[mi][2 * ks][0], c[mi][2 * ks][1], qh[mi][ks][0], ql[mi][ks][0]);
            split2(c[mi][2 * ks][2], c[mi][2 * ks][3], qh[mi][ks][1], ql[mi][ks][1]);
            split2(c[mi][2 * ks + 1][0], c[mi][2 * ks + 1][1], qh[mi][ks][2], ql[mi][ks][2]);
            split2(c[mi][2 * ks + 1][2], c[mi][2 * ks + 1][3], qh[mi][ks][3], ql[mi][ks][3]);
        }
    __syncthreads();
    loadW(Wkv + 512 + head * 64, 1024, 1.f);  // Wv
    __syncthreads();
    proj(c);          // V in regs
    storeC(c, Xh, Xl);  // V overwrites X (own rows only)
    __syncthreads();
    loadW(Wout + (size_t)head * 64 * 64, 64, 1.f);  // Wout slice [c][d]
    __syncthreads();

    // ---- attention: S (32-col chunks) -> exp -> P regs -> O += P@V ----
    float o[2][8][4];
#pragma unroll
    for (int mi = 0; mi < 2; mi++)
#pragma unroll
        for (int nt = 0; nt < 8; nt++)
#pragma unroll
            for (int i = 0; i < 4; i++) o[mi][nt][i] = 0.f;
    float lsum[4] = {0.f, 0.f, 0.f, 0.f};

    for (int jc = 0; jc < 8; jc++) {
        float s[2][4][4];
#pragma unroll
        for (int mi = 0; mi < 2; mi++)
#pragma unroll
            for (int jt = 0; jt < 4; jt++)
#pragma unroll
                for (int i = 0; i < 4; i++) s[mi][jt][i] = 0.f;
#pragma unroll
        for (int ks = 0; ks < 4; ks++) {
            uint32_t kbh[2][4], kbl[2][4];
            ldsm4(kbh[0], bAddrN(Kh, jc * 32, ks * 16));
            ldsm4(kbh[1], bAddrN(Kh, jc * 32 + 16, ks * 16));
            ldsm4(kbl[0], bAddrN(Kl, jc * 32, ks * 16));
            ldsm4(kbl[1], bAddrN(Kl, jc * 32 + 16, ks * 16));
#pragma unroll
            for (int mi = 0; mi < 2; mi++)
#pragma unroll
                for (int jt = 0; jt < 4; jt++) {
                    float* ss = s[mi][jt];
                    const uint32_t* bh = &kbh[jt >> 1][(jt & 1) * 2];
                    const uint32_t* bl = &kbl[jt >> 1][(jt & 1) * 2];
                    mma16816(ss, qh[mi][ks], bh);
                    mma16816(ss, ql[mi][ks], bh);
                    mma16816(ss, qh[mi][ks], bl);
                }
        }
        // exp (no max-sub: logits tiny by construction) + pack P fragments
        uint32_t ph[2][2][4], pl[2][2][4];
#pragma unroll
        for (int mi = 0; mi < 2; mi++)
#pragma unroll
            for (int k2 = 0; k2 < 2; k2++) {
                float e0 = __expf(s[mi][2 * k2][0]), e1 = __expf(s[mi][2 * k2][1]);
                float e2 = __expf(s[mi][2 * k2][2]), e3 = __expf(s[mi][2 * k2][3]);
                float f0 = __expf(s[mi][2 * k2 + 1][0]), f1 = __expf(s[mi][2 * k2 + 1][1]);
                float f2 = __expf(s[mi][2 * k2 + 1][2]), f3 = __expf(s[mi][2 * k2 + 1][3]);
                lsum[mi * 2 + 0] += e0 + e1 + f0 + f1;
                lsum[mi * 2 + 1] += e2 + e3 + f2 + f3;
                split2(e0, e1, ph[mi][k2][0], pl[mi][k2][0]);
                split2(e2, e3, ph[mi][k2][1], pl[mi][k2][1]);
                split2(f0, f1, ph[mi][k2][2], pl[mi][k2][2]);
                split2(f2, f3, ph[mi][k2][3], pl[mi][k2][3]);
            }
        // O += P @ V  (V lives where X was)
#pragma unroll
        for (int k2 = 0; k2 < 2; k2++) {
            int j0 = jc * 32 + k2 * 16;
#pragma unroll
            for (int np = 0; np < 4; np++) {
                uint32_t vb[4], vl[4];
                ldsm4t(vb, bAddrT(Xh, j0, np * 16));
                ldsm4t(vl, bAddrT(Xl, j0, np * 16));
#pragma unroll
                for (int mi = 0; mi < 2; mi++)
#pragma unroll
                    for (int hf = 0; hf < 2; hf++) {
                        float* oo = o[mi][np * 2 + hf];
                        mma16816(oo, ph[mi][k2], vb + hf * 2);
                        mma16816(oo, pl[mi][k2], vb + hf * 2);
                        mma16816(oo, ph[mi][k2], vl + hf * 2);
                    }
            }
        }
    }
    // row sums: reduce across the 4 lanes holding each row
#pragma unroll
    for (int i = 0; i < 4; i++) {
        lsum[i] += __shfl_xor_sync(0xffffffffu, lsum[i], 1);
        lsum[i] += __shfl_xor_sync(0xffffffffu, lsum[i], 2);
    }
    float inv[4];
#pragma unroll
    for (int i = 0; i < 4; i++) inv[i] = 1.f / lsum[i];
    // O*inv -> A fragments
    uint32_t oh[2][4][4], ol[2][4][4];
#pragma unroll
    for (int mi = 0; mi < 2; mi++)
#pragma unroll
        for (int ks = 0; ks < 4; ks++) {
            float i0 = inv[mi * 2], i1 = inv[mi * 2 + 1];
            split2(o[mi][2 * ks][0] * i0, o[mi][2 * ks][1] * i0, oh[mi][ks][0], ol[mi][ks][0]);
            split2(o[mi][2 * ks][2] * i1, o[mi][2 * ks][3] * i1, oh[mi][ks][1], ol[mi][ks][1]);
            split2(o[mi][2 * ks + 1][0] * i0, o[mi][2 * ks + 1][1] * i0, oh[mi][ks][2], ol[mi][ks][2]);
            split2(o[mi][2 * ks + 1][2] * i1, o[mi][2 * ks + 1][3] * i1, oh[mi][ks][3], ol[mi][ks][3]);
        }
    // out-projection
    float r[2][8][4];
#pragma unroll
    for (int mi = 0; mi < 2; mi++)
#pragma unroll
        for (int nt = 0; nt < 8; nt++)
#pragma unroll
            for (int i = 0; i < 4; i++) r[mi][nt][i] = 0.f;
#pragma unroll
    for (int ks = 0; ks < 4; ks++)
#pragma unroll
        for (int np = 0; np < 4; np++) {
            uint32_t bh[4], bl[4];
            ldsm4t(bh, bAddrT(Wh, ks * 16, np * 16));
            ldsm4t(bl, bAddrT(Wl, ks * 16, np * 16));
#pragma unroll
            for (int mi = 0; mi < 2; mi++)
#pragma unroll
                for (int hf = 0; hf < 2; hf++) {
                    float* rr = r[mi][np * 2 + hf];
                    mma16816(rr, oh[mi][ks], bh + hf * 2);
                    mma16816(rr, ol[mi][ks], bh + hf * 2);
                    mma16816(rr, oh[mi][ks], bl + hf * 2);
                }
        }
#pragma unroll
    for (int mi = 0; mi < 2; mi++)
#pragma unroll
        for (int nt = 0; nt < 8; nt++) {
            int row = m0 + mi * 16 + (lane >> 2), col = nt * 8 + ((lane & 3) << 1);
            float* op = out + ((size_t)row * WW + w) * DD;
            atomicAdd(op + col, 0.5f * r[mi][nt][0]);
            atomicAdd(op + col + 1, 0.5f * r[mi][nt][1]);
            float* op2 = out + ((size_t)(row + 8) * WW + w) * DD;
            atomicAdd(op2 + col, 0.5f * r[mi][nt][2]);
            atomicAdd(op2 + col + 1, 0.5f * r[mi][nt][3]);
        }
}

// ======================= fp32 height path (unchanged, passing) ===============
__global__ void k_init(const float* __restrict__ bw, const float* __restrict__ bh,
                       float* __restrict__ out) {
    int idx = blockIdx.x * 256 + threadIdx.x;
    out[idx] = 0.5f * (bw[idx & 63] + bh[idx & 63]);
}
__global__ void k_zero_dots() { g_DOTS[blockIdx.x * 256 + threadIdx.x] = 0.f; }

__device__ __forceinline__ void proj_row(const float* __restrict__ xs,
                                         const float* __restrict__ wt, int t, float* a) {
#pragma unroll
    for (int c = 0; c < 64; c++) a[c] = 0.f;
    for (int d = 0; d < 64; d++) {
        float xv = xs[d * 257 + t];
        const float4* wr = (const float4*)(wt + d * 68);
#pragma unroll
        for (int c4 = 0; c4 < 16; c4++) {
            float4 wv = wr[c4];
            a[c4 * 4 + 0] = fmaf(xv, wv.x, a[c4 * 4 + 0]);
            a[c4 * 4 + 1] = fmaf(xv, wv.y, a[c4 * 4 + 1]);
            a[c4 * 4 + 2] = fmaf(xv, wv.z, a[c4 * 4 + 2]);
            a[c4 * 4 + 3] = fmaf(xv, wv.w, a[c4 * 4 + 3]);
        }
    }
}

__global__ void __launch_bounds__(256, 1)
k_hproj(const float* __restrict__ x, const float* __restrict__ Wq,
        const float* __restrict__ Wkv) {
    extern __shared__ float smf[];
    float* xs = smf;
    float* wt = xs + 64 * 257;
    const int t = threadIdx.x, r = blockIdx.x;
    for (int e = t; e < HH * DD; e += 256) {
        int i = e >> 6, d = e & 63;
        xs[d * 257 + i] = x[(size_t)r * (WW * DD) + e];
    }
    __syncthreads();
    float a[64];
    for (int mk = 0; mk < 3; mk++) {
        for (int g = 0; g < 8; g++) {
            __syncthreads();
            for (int e = t; e < 4096; e += 256) {
                int d = e >> 6, c = e & 63;
                float wv;
                if (mk == 0) wv = Wq[d * 512 + g * 64 + c];
                else if (mk == 1) wv = Wkv[d * 1024 + g * 64 + c];
                else wv = Wkv[d * 1024 + 512 + g * 64 + c];
                wt[d * 68 + c] = wv;
            }
            __syncthreads();
            proj_row(xs, wt, t, a);
            float* dst;
            if (mk == 0) dst = g_QH + ((size_t)(g * 256 + t)) * KBIG + r * 64;
            else if (mk == 1) dst = g_KH + ((size_t)(g * 256 + t)) * KBIG + r * 64;
            else dst = g_VH + ((size_t)(r * 256 + t)) * INNER + g * 64;
            float4* d4 = (float4*)dst;
#pragma unroll
            for (int c4 = 0; c4 < 16; c4++)
                d4[c4] = make_float4(a[c4 * 4], a[c4 * 4 + 1], a[c4 * 4 + 2], a[c4 * 4 + 3]);
        }
    }
}

__global__ void k_pair(const float* __restrict__ pb, const float* __restrict__ g,
                       const float* __restrict__ b, const float* __restrict__ Wp) {
    __shared__ float swp[1024], sg[128], sb2[128];
    const int t = threadIdx.x;
    if (t < 128) { sg[t] = g[t]; sb2[t] = b[t]; }
    for (int e = t; e < 1024; e += 256) swp[e] = Wp[e];
    __syncthreads();
    const int warp = t >> 5, lane = t & 31;
    const int gw = blockIdx.x * 8 + warp;
    const int i = gw >> 8, j = gw & 255;
    const float4* src = (const float4*)(pb + (size_t)gw * 128);
    float4 v = src[lane];
    float s1 = v.x + v.y + v.z + v.w;
    float s2 = v.x * v.x + v.y * v.y + v.z * v.z + v.w * v.w;
#pragma unroll
    for (int o = 16; o; o >>= 1) {
        s1 += __shfl_xor_sync(0xffffffffu, s1, o);
        s2 += __shfl_xor_sync(0xffffffffu, s2, o);
    }
    float mu = s1 * (1.f / 128.f);
    float rstd = rsqrtf(s2 * (1.f / 128.f) - mu * mu + 1e-5f);
    float phd[8];
#pragma unroll
    for (int h = 0; h < 8; h++) phd[h] = 0.f;
    float vv[4] = {v.x, v.y, v.z, v.w};
#pragma unroll
    for (int qi = 0; qi < 4; qi++) {
        int p = lane * 4 + qi;
        float n = (vv[qi] - mu) * rstd * sg[p] + sb2[p];
#pragma unroll
        for (int h = 0; h < 8; h++) phd[h] = fmaf(n, swp[p * 8 + h], phd[h]);
    }
#pragma unroll
    for (int h = 0; h < 8; h++)
#pragma unroll
        for (int o = 16; o; o >>= 1) phd[h] += __shfl_xor_sync(0xffffffffu, phd[h], o);
    if (lane == 0)
#pragma unroll
        for (int h = 0; h < 8; h++) g_PB[h * 65536 + i * 256 + j] = phd[h];
}

__global__ void __launch_bounds__(256, 1) k_hdots() {
    extern __shared__ float smf[];
    float* Qs = smf;
    float* Ks = Qs + 64 * 68;
    const int t = threadIdx.x, kc = blockIdx.x, it = blockIdx.y, head = blockIdx.z;
    const int i0 = it * 64, tx = t & 31, ty = t >> 5;
    float acc[64];
#pragma unroll
    for (int c = 0; c < 64; c++) acc[c] = 0.f;
    for (int stp = 0; stp < 32; stp++) {
        const int k0 = kc * 2048 + stp * 64;
        __syncthreads();
        for (int e = t; e < 4096; e += 256) {
            int ii = e >> 6, kk = e & 63;
            Qs[ii * 68 + kk] = g_QH[(size_t)(head * 256 + i0 + ii) * KBIG + k0 + kk];
        }
        for (int e = t; e < 16384; e += 256) {
            int j = e >> 6, kk = e & 63;
            Ks[j * 68 + kk] = g_KH[(size_t)(head * 256 + j) * KBIG + k0 + kk];
        }
        __syncthreads();
        for (int kk = 0; kk < 64; kk += 4) {
            float4 aq[8], bk[8];
#pragma unroll
            for (int ii = 0; ii < 8; ii++) aq[ii] = *(const float4*)(Qs + (ty * 8 + ii) * 68 + kk);
#pragma unroll
            for (int jj = 0; jj < 8; jj++) bk[jj] = *(const float4*)(Ks + (tx + jj * 32) * 68 + kk);
#pragma unroll
            for (int ii = 0; ii < 8; ii++)
#pragma unroll
                for (int jj = 0; jj < 8; jj++) {
                    float s = acc[ii * 8 + jj];
                    s = fmaf(aq[ii].x, bk[jj].x, s);
                    s = fmaf(aq[ii].y, bk[jj].y, s);
                    s = fmaf(aq[ii].z, bk[jj].z, s);
                    s = fmaf(aq[ii].w, bk[jj].w, s);
                    acc[ii * 8 + jj] = s;
                }
        }
    }
#pragma unroll
    for (int ii = 0; ii < 8; ii++)
#pragma unroll
        for (int jj = 0; jj < 8; jj++)
            atomicAdd(&g_DOTS[head * 65536 + (i0 + ty * 8 + ii) * 256 + tx + jj * 32], acc[ii * 8 + jj]);
}

__global__ void k_hsm() {
    const int t = threadIdx.x, warp = t >> 5, lane = t & 31;
    const int row = blockIdx.x * 8 + warp;
    float v[8];
    float mx = -1e30f;
#pragma unroll
    for (int kk = 0; kk < 8; kk++) {
        int j = kk * 32 + lane;
        v[kk] = g_DOTS[row * 256 + j] * 0.0078125f + g_PB[row * 256 + j];
        mx = fmaxf(mx, v[kk]);
    }
#pragma unroll
    for (int o = 16; o; o >>= 1) mx = fmaxf(mx, __shfl_xor_sync(0xffffffffu, mx, o));
    float s = 0.f;
#pragma unroll
    for (int kk = 0; kk < 8; kk++) { v[kk] = __expf(v[kk] - mx); s += v[kk]; }
#pragma unroll
    for (int o = 16; o; o >>= 1) s += __shfl_xor_sync(0xffffffffu, s, o);
    float inv = 1.f / s;
#pragma unroll
    for (int kk = 0; kk < 8; kk++) g_DOTS[row * 256 + kk * 32 + lane] = v[kk] * inv;
}

__global__ void __launch_bounds__(256, 1)
k_hav(const float* __restrict__ Wout, float* __restrict__ out) {
    extern __shared__ float smf[];
    float* vs = smf;
    float* ats = vs + 256 * 68;
    float* wt = ats + 256 * 68;
    const int t = threadIdx.x, r = blockIdx.x, head = blockIdx.y;
    for (int e = t; e < 16384; e += 256) {
        int j = e >> 6, c = e & 63;
        vs[j * 68 + c] = g_VH[(size_t)(r * 256 + j) * INNER + head * 64 + c];
    }
    for (int e = t; e < 4096; e += 256) {
        int c = e >> 6, d = e & 63;
        wt[c * 68 + d] = Wout[(head * 64 + c) * 64 + d];
    }
    float acc[64];
#pragma unroll
    for (int c = 0; c < 64; c++) acc[c] = 0.f;
    for (int jt = 0; jt < 4; jt++) {
        __syncthreads();
        for (int e = t; e < 16384; e += 256) {
            int ii = e >> 6, jj = e & 63;
            ats[ii * 68 + jj] = g_DOTS[head * 65536 + ii * 256 + jt * 64 + jj];
        }
        __syncthreads();
        for (int jj4 = 0; jj4 < 16; jj4++) {
            float4 p4 = *(const float4*)(ats + t * 68 + jj4 * 4);
            float pv[4] = {p4.x, p4.y, p4.z, p4.w};
#pragma unroll
            for (int u = 0; u < 4; u++) {
                float p = pv[u];
                const float4* vr = (const float4*)(vs + (size_t)(jt * 64 + jj4 * 4 + u) * 68);
#pragma unroll
                for (int c4 = 0; c4 < 16; c4++) {
                    float4 vvv = vr[c4];
                    acc[c4 * 4 + 0] = fmaf(p, vvv.x, acc[c4 * 4 + 0]);
                    acc[c4 * 4 + 1] = fmaf(p, vvv.y, acc[c4 * 4 + 1]);
                    acc[c4 * 4 + 2] = fmaf(p, vvv.z, acc[c4 * 4 + 2]);
                    acc[c4 * 4 + 3] = fmaf(p, vvv.w, acc[c4 * 4 + 3]);
                }
            }
        }
    }
    float oc[64];
#pragma unroll
    for (int d = 0; d < 64; d++) oc[d] = 0.f;
#pragma unroll
    for (int c = 0; c < 64; c++) {
        float ov = acc[c];
        const float4* wr = (const float4*)(wt + c * 68);
#pragma unroll
        for (int d4 = 0; d4 < 16; d4++) {
            float4 wv = wr[d4];
            oc[d4 * 4 + 0] = fmaf(ov, wv.x, oc[d4 * 4 + 0]);
            oc[d4 * 4 + 1] = fmaf(ov, wv.y, oc[d4 * 4 + 1]);
            oc[d4 * 4 + 2] = fmaf(ov, wv.z, oc[d4 * 4 + 2]);
            oc[d4 * 4 + 3] = fmaf(ov, wv.w, oc[d4 * 4 + 3]);
        }
    }
    float* op = out + ((size_t)r * WW + t) * DD;
#pragma unroll
    for (int d = 0; d < 64; d++) atomicAdd(op + d, 0.5f * oc[d]);
}

// ============================================================================
extern "C" void kernel_launch(void* const* d_in, const int* in_sizes, int n_in,
                              void* d_out, int out_size) {
    (void)in_sizes; (void)n_in; (void)out_size;
    const float* x = (const float*)d_in[0];
    const float* pb = (const float*)d_in[1];
    const float* Wq_w = (const float*)d_in[2];
    const float* Wkv_w = (const float*)d_in[3];
    const float* Wout_w = (const float*)d_in[4];
    const float* bout_w = (const float*)d_in[5];
    const float* Wq_h = (const float*)d_in[6];
    const float* Wkv_h = (const float*)d_in[7];
    const float* Wout_h = (const float*)d_in[8];
    const float* bout_h = (const float*)d_in[9];
    const float* lng = (const float*)d_in[10];
    const float* lnb = (const float*)d_in[11];
    const float* Wp = (const float*)d_in[12];
    float* out = (float*)d_out;

    const int smw = (4 * 256 * XS + 2 * 64 * XS) * (int)sizeof(__nv_bfloat16);  // 165888
    const int smp = (64 * 257 + 64 * 68) * (int)sizeof(float);
    const int smd = (64 * 68 + 256 * 68) * (int)sizeof(float);
    const int sma = (256 * 68 * 2 + 64 * 68) * (int)sizeof(float);
    cudaFuncSetAttribute(k_width_mma, cudaFuncAttributeMaxDynamicSharedMemorySize, smw);
    cudaFuncSetAttribute(k_hproj, cudaFuncAttributeMaxDynamicSharedMemorySize, smp);
    cudaFuncSetAttribute(k_hdots, cudaFuncAttributeMaxDynamicSharedMemorySize, smd);
    cudaFuncSetAttribute(k_hav, cudaFuncAttributeMaxDynamicSharedMemorySize, sma);

    k_init<<<16384, 256>>>(bout_w, bout_h, out);
    k_zero_dots<<<2048, 256>>>();
    k_width_mma<<<dim3(256, 8), 256, smw>>>(x, Wq_w, Wkv_w, Wout_w, out);
    k_hproj<<<256, 256, smp>>>(x, Wq_h, Wkv_h);
    k_pair<<<8192, 256>>>(pb, lng, lnb, Wp);
    k_hdots<<<dim3(8, 4, 8), 256, smd>>>();
    k_hsm<<<256, 256>>>();
    k_hav<<<dim3(256, 8), 256, sma>>>(Wout_h, out);
}

// round 5
// speedup vs baseline: 1.4862x; 1.4862x over previous
#include <cuda_runtime.h>
#include <cuda_bf16.h>
#include <cstdint>
#include <math.h>

#define HH 256
#define WW 256
#define DD 64
#define NH 8
#define INNER 512
#define KBIG 16384

__device__ float g_QH[NH * WW * HH * 64];
__device__ float g_KH[NH * WW * HH * 64];
__device__ float g_VH[HH * WW * INNER];
__device__ float g_DOTS[NH * WW * WW];
__device__ float g_PB[NH * WW * WW];

// ---------------- warp-MMA helpers ------------------------------------------
__device__ __forceinline__ void ldsm4(uint32_t* r, uint32_t a) {
    asm volatile("ldmatrix.sync.aligned.m8n8.x4.shared.b16 {%0,%1,%2,%3}, [%4];"
                 : "=r"(r[0]), "=r"(r[1]), "=r"(r[2]), "=r"(r[3]) : "r"(a));
}
__device__ __forceinline__ void ldsm4t(uint32_t* r, uint32_t a) {
    asm volatile("ldmatrix.sync.aligned.m8n8.x4.trans.shared.b16 {%0,%1,%2,%3}, [%4];"
                 : "=r"(r[0]), "=r"(r[1]), "=r"(r[2]), "=r"(r[3]) : "r"(a));
}
__device__ __forceinline__ void mma16816(float* c, const uint32_t* a, const uint32_t* b) {
    asm volatile("mma.sync.aligned.m16n8k16.row.col.f32.bf16.bf16.f32 "
                 "{%0,%1,%2,%3},{%4,%5,%6,%7},{%8,%9},{%0,%1,%2,%3};"
                 : "+f"(c[0]), "+f"(c[1]), "+f"(c[2]), "+f"(c[3])
                 : "r"(a[0]), "r"(a[1]), "r"(a[2]), "r"(a[3]), "r"(b[0]), "r"(b[1]));
}
__device__ __forceinline__ void split2(float a, float b, uint32_t& h, uint32_t& l) {
    __nv_bfloat162 hv = __floats2bfloat162_rn(a, b);
    float2 hf = __bfloat1622float2(hv);
    __nv_bfloat162 lv = __floats2bfloat162_rn(a - hf.x, b - hf.y);
    h = *reinterpret_cast<uint32_t*>(&hv);
    l = *reinterpret_cast<uint32_t*>(&lv);
}

#define XS 72

// ============================================================================
// Width attention, mma.sync bf16 split-3. Block=(w,head). 16 warps x 16 rows.
// ============================================================================
__global__ void __launch_bounds__(512, 1)
k_width_mma(const float* __restrict__ x, const float* __restrict__ Wq,
            const float* __restrict__ Wkv, const float* __restrict__ Wout,
            float* __restrict__ out) {
    extern __shared__ __nv_bfloat16 sb[];
    __nv_bfloat16* Xh = sb;                 // later: V hi
    __nv_bfloat16* Xl = sb + 256 * XS;      // later: V lo
    __nv_bfloat16* Kh = sb + 2 * 256 * XS;
    __nv_bfloat16* Kl = sb + 3 * 256 * XS;
    __nv_bfloat16* Wh = sb + 4 * 256 * XS;
    __nv_bfloat16* Wl = Wh + 64 * XS;

    const int t = threadIdx.x, lane = t & 31, warp = t >> 5, m0 = warp * 16;
    const int w = blockIdx.x, head = blockIdx.y;

    // ---- X column w -> bf16 hi/lo (each thread: half a row) ----
    {
        int row = t >> 1, q0 = (t & 1) * 8;
        const float4* src = (const float4*)(x + (size_t)row * (WW * DD) + w * DD) + q0;
#pragma unroll
        for (int q4 = 0; q4 < 8; q4++) {
            float4 v = src[q4];
            uint32_t h0, l0, h1, l1;
            split2(v.x, v.y, h0, l0);
            split2(v.z, v.w, h1, l1);
            int cc = (q0 + q4) * 4;
            *(uint32_t*)(Xh + row * XS + cc) = h0;
            *(uint32_t*)(Xh + row * XS + cc + 2) = h1;
            *(uint32_t*)(Xl + row * XS + cc) = l0;
            *(uint32_t*)(Xl + row * XS + cc + 2) = l1;
        }
    }
    auto loadW = [&](const float* wsrc, int stride, float scale) {
        for (int e = t; e < 2048; e += 512) {
            int k = e >> 5, n2 = e & 31;
            float2 v = *(const float2*)(wsrc + (size_t)k * stride + n2 * 2);
            uint32_t h, l;
            split2(v.x * scale, v.y * scale, h, l);
            *(uint32_t*)(Wh + k * XS + n2 * 2) = h;
            *(uint32_t*)(Wl + k * XS + n2 * 2) = l;
        }
    };
    auto aAddr = [&](const __nv_bfloat16* base, int r0, int k0) -> uint32_t {
        int row = r0 + (lane & 15), col = k0 + ((lane >> 4) << 3);
        return (uint32_t)__cvta_generic_to_shared(base + row * XS + col);
    };
    auto bAddrT = [&](const __nv_bfloat16* base, int k0, int n0) -> uint32_t {
        int row = k0 + (lane & 7) + (((lane >> 3) & 1) << 3);
        int col = n0 + ((lane >> 4) << 3);
        return (uint32_t)__cvta_generic_to_shared(base + row * XS + col);
    };
    auto bAddrN = [&](const __nv_bfloat16* base, int j0, int d0) -> uint32_t {
        int row = j0 + (lane & 7) + ((lane >> 4) << 3);
        int col = d0 + (((lane >> 3) & 1) << 3);
        return (uint32_t)__cvta_generic_to_shared(base + row * XS + col);
    };
    // C[16x64] = X[16 own rows] @ W, 3-term split
    auto proj = [&](float (&c)[8][4]) {
#pragma unroll
        for (int nt = 0; nt < 8; nt++)
#pragma unroll
            for (int i = 0; i < 4; i++) c[nt][i] = 0.f;
#pragma unroll
        for (int ks = 0; ks < 4; ks++) {
            uint32_t ah[4], al[4];
            ldsm4(ah, aAddr(Xh, m0, ks * 16));
            ldsm4(al, aAddr(Xl, m0, ks * 16));
#pragma unroll
            for (int np = 0; np < 4; np++) {
                uint32_t bh[4], bl[4];
                ldsm4t(bh, bAddrT(Wh, ks * 16, np * 16));
                ldsm4t(bl, bAddrT(Wl, ks * 16, np * 16));
#pragma unroll
                for (int hf = 0; hf < 2; hf++) {
                    float* cc = c[np * 2 + hf];
                    mma16816(cc, ah, bh + hf * 2);
                    mma16816(cc, al, bh + hf * 2);
                    mma16816(cc, ah, bl + hf * 2);
                }
            }
        }
    };
    auto storeC = [&](float (&c)[8][4], __nv_bfloat16* Dh, __nv_bfloat16* Dl) {
#pragma unroll
        for (int nt = 0; nt < 8; nt++) {
            int r = m0 + (lane >> 2), cc = nt * 8 + ((lane & 3) << 1);
            uint32_t h, l;
            split2(c[nt][0], c[nt][1], h, l);
            *(uint32_t*)(Dh + r * XS + cc) = h;
            *(uint32_t*)(Dl + r * XS + cc) = l;
            split2(c[nt][2], c[nt][3], h, l);
            *(uint32_t*)(Dh + (r + 8) * XS + cc) = h;
            *(uint32_t*)(Dl + (r + 8) * XS + cc) = l;
        }
    };

    float c[8][4];
    loadW(Wkv + head * 64, 1024, 1.f);  // Wk
    __syncthreads();
    proj(c);
    storeC(c, Kh, Kl);
    __syncthreads();
    loadW(Wq + head * 64, 512, 0.125f);  // Wq, scale folded
    __syncthreads();
    proj(c);
    uint32_t qh[4][4], ql[4][4];
#pragma unroll
    for (int ks = 0; ks < 4; ks++) {
        split2(c[2 * ks][0], c[2 * ks][1], qh[ks][0], ql[ks][0]);
        split2(c[2 * ks][2], c[2 * ks][3], qh[ks][1], ql[ks][1]);
        split2(c[2 * ks + 1][0], c[2 * ks + 1][1], qh[ks][2], ql[ks][2]);
        split2(c[2 * ks + 1][2], c[2 * ks + 1][3], qh[ks][3], ql[ks][3]);
    }
    __syncthreads();
    loadW(Wkv + 512 + head * 64, 1024, 1.f);  // Wv
    __syncthreads();
    proj(c);
    storeC(c, Xh, Xl);  // V overwrites X
    __syncthreads();
    loadW(Wout + (size_t)head * 64 * 64, 64, 1.f);  // Wout slice
    __syncthreads();

    // ---- attention: per 32-key chunk: S -> exp -> P -> O += P@V ----
    float o[8][4];
#pragma unroll
    for (int nt = 0; nt < 8; nt++)
#pragma unroll
        for (int i = 0; i < 4; i++) o[nt][i] = 0.f;
    float lsum[2] = {0.f, 0.f};

    for (int jc = 0; jc < 8; jc++) {
        float s[4][4];
#pragma unroll
        for (int jt = 0; jt < 4; jt++)
#pragma unroll
            for (int i = 0; i < 4; i++) s[jt][i] = 0.f;
#pragma unroll
        for (int ks = 0; ks < 4; ks++) {
            uint32_t kbh[2][4], kbl[2][4];
            ldsm4(kbh[0], bAddrN(Kh, jc * 32, ks * 16));
            ldsm4(kbh[1], bAddrN(Kh, jc * 32 + 16, ks * 16));
            ldsm4(kbl[0], bAddrN(Kl, jc * 32, ks * 16));
            ldsm4(kbl[1], bAddrN(Kl, jc * 32 + 16, ks * 16));
#pragma unroll
            for (int jt = 0; jt < 4; jt++) {
                float* ss = s[jt];
                const uint32_t* bh = &kbh[jt >> 1][(jt & 1) * 2];
                const uint32_t* bl = &kbl[jt >> 1][(jt & 1) * 2];
                mma16816(ss, qh[ks], bh);
                mma16816(ss, ql[ks], bh);
                mma16816(ss, qh[ks], bl);
            }
        }
        uint32_t ph[2][4], pl[2][4];
#pragma unroll
        for (int k2 = 0; k2 < 2; k2++) {
            float e0 = __expf(s[2 * k2][0]), e1 = __expf(s[2 * k2][1]);
            float e2 = __expf(s[2 * k2][2]), e3 = __expf(s[2 * k2][3]);
            float f0 = __expf(s[2 * k2 + 1][0]), f1 = __expf(s[2 * k2 + 1][1]);
            float f2 = __expf(s[2 * k2 + 1][2]), f3 = __expf(s[2 * k2 + 1][3]);
            lsum[0] += e0 + e1 + f0 + f1;
            lsum[1] += e2 + e3 + f2 + f3;
            split2(e0, e1, ph[k2][0], pl[k2][0]);
            split2(e2, e3, ph[k2][1], pl[k2][1]);
            split2(f0, f1, ph[k2][2], pl[k2][2]);
            split2(f2, f3, ph[k2][3], pl[k2][3]);
        }
#pragma unroll
        for (int k2 = 0; k2 < 2; k2++) {
            int j0 = jc * 32 + k2 * 16;
#pragma unroll
            for (int np = 0; np < 4; np++) {
                uint32_t vb[4], vl[4];
                ldsm4t(vb, bAddrT(Xh, j0, np * 16));
                ldsm4t(vl, bAddrT(Xl, j0, np * 16));
#pragma unroll
                for (int hf = 0; hf < 2; hf++) {
                    float* oo = o[np * 2 + hf];
                    mma16816(oo, ph[k2], vb + hf * 2);
                    mma16816(oo, pl[k2], vb + hf * 2);
                    mma16816(oo, ph[k2], vl + hf * 2);
                }
            }
        }
    }
#pragma unroll
    for (int i = 0; i < 2; i++) {
        lsum[i] += __shfl_xor_sync(0xffffffffu, lsum[i], 1);
        lsum[i] += __shfl_xor_sync(0xffffffffu, lsum[i], 2);
    }
    float i0 = 1.f / lsum[0], i1 = 1.f / lsum[1];
    uint32_t oh[4][4], ol[4][4];
#pragma unroll
    for (int ks = 0; ks < 4; ks++) {
        split2(o[2 * ks][0] * i0, o[2 * ks][1] * i0, oh[ks][0], ol[ks][0]);
        split2(o[2 * ks][2] * i1, o[2 * ks][3] * i1, oh[ks][1], ol[ks][1]);
        split2(o[2 * ks + 1][0] * i0, o[2 * ks + 1][1] * i0, oh[ks][2], ol[ks][2]);
        split2(o[2 * ks + 1][2] * i1, o[2 * ks + 1][3] * i1, oh[ks][3], ol[ks][3]);
    }
    float r[8][4];
#pragma unroll
    for (int nt = 0; nt < 8; nt++)
#pragma unroll
        for (int i = 0; i < 4; i++) r[nt][i] = 0.f;
#pragma unroll
    for (int ks = 0; ks < 4; ks++)
#pragma unroll
        for (int np = 0; np < 4; np++) {
            uint32_t bh[4], bl[4];
            ldsm4t(bh, bAddrT(Wh, ks * 16, np * 16));
            ldsm4t(bl, bAddrT(Wl, ks * 16, np * 16));
#pragma unroll
            for (int hf = 0; hf < 2; hf++) {
                float* rr = r[np * 2 + hf];
                mma16816(rr, oh[ks], bh + hf * 2);
                mma16816(rr, ol[ks], bh + hf * 2);
                mma16816(rr, oh[ks], bl + hf * 2);
            }
        }
#pragma unroll
    for (int nt = 0; nt < 8; nt++) {
        int row = m0 + (lane >> 2), col = nt * 8 + ((lane & 3) << 1);
        float* op = out + ((size_t)row * WW + w) * DD;
        atomicAdd(op + col, 0.5f * r[nt][0]);
        atomicAdd(op + col + 1, 0.5f * r[nt][1]);
        float* op2 = out + ((size_t)(row + 8) * WW + w) * DD;
        atomicAdd(op2 + col, 0.5f * r[nt][2]);
        atomicAdd(op2 + col + 1, 0.5f * r[nt][3]);
    }
}

// ======================= fp32 height path (unchanged, passing) ===============
__global__ void k_init(const float* __restrict__ bw, const float* __restrict__ bh,
                       float* __restrict__ out) {
    int idx = blockIdx.x * 256 + threadIdx.x;
    out[idx] = 0.5f * (bw[idx & 63] + bh[idx & 63]);
}
__global__ void k_zero_dots() { g_DOTS[blockIdx.x * 256 + threadIdx.x] = 0.f; }

__device__ __forceinline__ void proj_row(const float* __restrict__ xs,
                                         const float* __restrict__ wt, int t, float* a) {
#pragma unroll
    for (int c = 0; c < 64; c++) a[c] = 0.f;
    for (int d = 0; d < 64; d++) {
        float xv = xs[d * 257 + t];
        const float4* wr = (const float4*)(wt + d * 68);
#pragma unroll
        for (int c4 = 0; c4 < 16; c4++) {
            float4 wv = wr[c4];
            a[c4 * 4 + 0] = fmaf(xv, wv.x, a[c4 * 4 + 0]);
            a[c4 * 4 + 1] = fmaf(xv, wv.y, a[c4 * 4 + 1]);
            a[c4 * 4 + 2] = fmaf(xv, wv.z, a[c4 * 4 + 2]);
            a[c4 * 4 + 3] = fmaf(xv, wv.w, a[c4 * 4 + 3]);
        }
    }
}

__global__ void __launch_bounds__(256, 1)
k_hproj(const float* __restrict__ x, const float* __restrict__ Wq,
        const float* __restrict__ Wkv) {
    extern __shared__ float smf[];
    float* xs = smf;
    float* wt = xs + 64 * 257;
    const int t = threadIdx.x, r = blockIdx.x;
    for (int e = t; e < HH * DD; e += 256) {
        int i = e >> 6, d = e & 63;
        xs[d * 257 + i] = x[(size_t)r * (WW * DD) + e];
    }
    __syncthreads();
    float a[64];
    for (int mk = 0; mk < 3; mk++) {
        for (int g = 0; g < 8; g++) {
            __syncthreads();
            for (int e = t; e < 4096; e += 256) {
                int d = e >> 6, c = e & 63;
                float wv;
                if (mk == 0) wv = Wq[d * 512 + g * 64 + c];
                else if (mk == 1) wv = Wkv[d * 1024 + g * 64 + c];
                else wv = Wkv[d * 1024 + 512 + g * 64 + c];
                wt[d * 68 + c] = wv;
            }
            __syncthreads();
            proj_row(xs, wt, t, a);
            float* dst;
            if (mk == 0) dst = g_QH + ((size_t)(g * 256 + t)) * KBIG + r * 64;
            else if (mk == 1) dst = g_KH + ((size_t)(g * 256 + t)) * KBIG + r * 64;
            else dst = g_VH + ((size_t)(r * 256 + t)) * INNER + g * 64;
            float4* d4 = (float4*)dst;
#pragma unroll
            for (int c4 = 0; c4 < 16; c4++)
                d4[c4] = make_float4(a[c4 * 4], a[c4 * 4 + 1], a[c4 * 4 + 2], a[c4 * 4 + 3]);
        }
    }
}

__global__ void k_pair(const float* __restrict__ pb, const float* __restrict__ g,
                       const float* __restrict__ b, const float* __restrict__ Wp) {
    __shared__ float swp[1024], sg[128], sb2[128];
    const int t = threadIdx.x;
    if (t < 128) { sg[t] = g[t]; sb2[t] = b[t]; }
    for (int e = t; e < 1024; e += 256) swp[e] = Wp[e];
    __syncthreads();
    const int warp = t >> 5, lane = t & 31;
    const int gw = blockIdx.x * 8 + warp;
    const int i = gw >> 8, j = gw & 255;
    const float4* src = (const float4*)(pb + (size_t)gw * 128);
    float4 v = src[lane];
    float s1 = v.x + v.y + v.z + v.w;
    float s2 = v.x * v.x + v.y * v.y + v.z * v.z + v.w * v.w;
#pragma unroll
    for (int o = 16; o; o >>= 1) {
        s1 += __shfl_xor_sync(0xffffffffu, s1, o);
        s2 += __shfl_xor_sync(0xffffffffu, s2, o);
    }
    float mu = s1 * (1.f / 128.f);
    float rstd = rsqrtf(s2 * (1.f / 128.f) - mu * mu + 1e-5f);
    float phd[8];
#pragma unroll
    for (int h = 0; h < 8; h++) phd[h] = 0.f;
    float vv[4] = {v.x, v.y, v.z, v.w};
#pragma unroll
    for (int qi = 0; qi < 4; qi++) {
        int p = lane * 4 + qi;
        float n = (vv[qi] - mu) * rstd * sg[p] + sb2[p];
#pragma unroll
        for (int h = 0; h < 8; h++) phd[h] = fmaf(n, swp[p * 8 + h], phd[h]);
    }
#pragma unroll
    for (int h = 0; h < 8; h++)
#pragma unroll
        for (int o = 16; o; o >>= 1) phd[h] += __shfl_xor_sync(0xffffffffu, phd[h], o);
    if (lane == 0)
#pragma unroll
        for (int h = 0; h < 8; h++) g_PB[h * 65536 + i * 256 + j] = phd[h];
}

__global__ void __launch_bounds__(256, 1) k_hdots() {
    extern __shared__ float smf[];
    float* Qs = smf;
    float* Ks = Qs + 64 * 68;
    const int t = threadIdx.x, kc = blockIdx.x, it = blockIdx.y, head = blockIdx.z;
    const int i0 = it * 64, tx = t & 31, ty = t >> 5;
    float acc[64];
#pragma unroll
    for (int c = 0; c < 64; c++) acc[c] = 0.f;
    for (int stp = 0; stp < 32; stp++) {
        const int k0 = kc * 2048 + stp * 64;
        __syncthreads();
        for (int e = t; e < 4096; e += 256) {
            int ii = e >> 6, kk = e & 63;
            Qs[ii * 68 + kk] = g_QH[(size_t)(head * 256 + i0 + ii) * KBIG + k0 + kk];
        }
        for (int e = t; e < 16384; e += 256) {
            int j = e >> 6, kk = e & 63;
            Ks[j * 68 + kk] = g_KH[(size_t)(head * 256 + j) * KBIG + k0 + kk];
        }
        __syncthreads();
        for (int kk = 0; kk < 64; kk += 4) {
            float4 aq[8], bk[8];
#pragma unroll
            for (int ii = 0; ii < 8; ii++) aq[ii] = *(const float4*)(Qs + (ty * 8 + ii) * 68 + kk);
#pragma unroll
            for (int jj = 0; jj < 8; jj++) bk[jj] = *(const float4*)(Ks + (tx + jj * 32) * 68 + kk);
#pragma unroll
            for (int ii = 0; ii < 8; ii++)
#pragma unroll
                for (int jj = 0; jj < 8; jj++) {
                    float s = acc[ii * 8 + jj];
                    s = fmaf(aq[ii].x, bk[jj].x, s);
                    s = fmaf(aq[ii].y, bk[jj].y, s);
                    s = fmaf(aq[ii].z, bk[jj].z, s);
                    s = fmaf(aq[ii].w, bk[jj].w, s);
                    acc[ii * 8 + jj] = s;
                }
        }
    }
#pragma unroll
    for (int ii = 0; ii < 8; ii++)
#pragma unroll
        for (int jj = 0; jj < 8; jj++)
            atomicAdd(&g_DOTS[head * 65536 + (i0 + ty * 8 + ii) * 256 + tx + jj * 32], acc[ii * 8 + jj]);
}

__global__ void k_hsm() {
    const int t = threadIdx.x, warp = t >> 5, lane = t & 31;
    const int row = blockIdx.x * 8 + warp;
    float v[8];
    float mx = -1e30f;
#pragma unroll
    for (int kk = 0; kk < 8; kk++) {
        int j = kk * 32 + lane;
        v[kk] = g_DOTS[row * 256 + j] * 0.0078125f + g_PB[row * 256 + j];
        mx = fmaxf(mx, v[kk]);
    }
#pragma unroll
    for (int o = 16; o; o >>= 1) mx = fmaxf(mx, __shfl_xor_sync(0xffffffffu, mx, o));
    float s = 0.f;
#pragma unroll
    for (int kk = 0; kk < 8; kk++) { v[kk] = __expf(v[kk] - mx); s += v[kk]; }
#pragma unroll
    for (int o = 16; o; o >>= 1) s += __shfl_xor_sync(0xffffffffu, s, o);
    float inv = 1.f / s;
#pragma unroll
    for (int kk = 0; kk < 8; kk++) g_DOTS[row * 256 + kk * 32 + lane] = v[kk] * inv;
}

__global__ void __launch_bounds__(256, 1)
k_hav(const float* __restrict__ Wout, float* __restrict__ out) {
    extern __shared__ float smf[];
    float* vs = smf;
    float* ats = vs + 256 * 68;
    float* wt = ats + 256 * 68;
    const int t = threadIdx.x, r = blockIdx.x, head = blockIdx.y;
    for (int e = t; e < 16384; e += 256) {
        int j = e >> 6, c = e & 63;
        vs[j * 68 + c] = g_VH[(size_t)(r * 256 + j) * INNER + head * 64 + c];
    }
    for (int e = t; e < 4096; e += 256) {
        int c = e >> 6, d = e & 63;
        wt[c * 68 + d] = Wout[(head * 64 + c) * 64 + d];
    }
    float acc[64];
#pragma unroll
    for (int c = 0; c < 64; c++) acc[c] = 0.f;
    for (int jt = 0; jt < 4; jt++) {
        __syncthreads();
        for (int e = t; e < 16384; e += 256) {
            int ii = e >> 6, jj = e & 63;
            ats[ii * 68 + jj] = g_DOTS[head * 65536 + ii * 256 + jt * 64 + jj];
        }
        __syncthreads();
        for (int jj4 = 0; jj4 < 16; jj4++) {
            float4 p4 = *(const float4*)(ats + t * 68 + jj4 * 4);
            float pv[4] = {p4.x, p4.y, p4.z, p4.w};
#pragma unroll
            for (int u = 0; u < 4; u++) {
                float p = pv[u];
                const float4* vr = (const float4*)(vs + (size_t)(jt * 64 + jj4 * 4 + u) * 68);
#pragma unroll
                for (int c4 = 0; c4 < 16; c4++) {
                    float4 vvv = vr[c4];
                    acc[c4 * 4 + 0] = fmaf(p, vvv.x, acc[c4 * 4 + 0]);
                    acc[c4 * 4 + 1] = fmaf(p, vvv.y, acc[c4 * 4 + 1]);
                    acc[c4 * 4 + 2] = fmaf(p, vvv.z, acc[c4 * 4 + 2]);
                    acc[c4 * 4 + 3] = fmaf(p, vvv.w, acc[c4 * 4 + 3]);
                }
            }
        }
    }
    float oc[64];
#pragma unroll
    for (int d = 0; d < 64; d++) oc[d] = 0.f;
#pragma unroll
    for (int c = 0; c < 64; c++) {
        float ov = acc[c];
        const float4* wr = (const float4*)(wt + c * 68);
#pragma unroll
        for (int d4 = 0; d4 < 16; d4++) {
            float4 wv = wr[d4];
            oc[d4 * 4 + 0] = fmaf(ov, wv.x, oc[d4 * 4 + 0]);
            oc[d4 * 4 + 1] = fmaf(ov, wv.y, oc[d4 * 4 + 1]);
            oc[d4 * 4 + 2] = fmaf(ov, wv.z, oc[d4 * 4 + 2]);
            oc[d4 * 4 + 3] = fmaf(ov, wv.w, oc[d4 * 4 + 3]);
        }
    }
    float* op = out + ((size_t)r * WW + t) * DD;
#pragma unroll
    for (int d = 0; d < 64; d++) atomicAdd(op + d, 0.5f * oc[d]);
}

// ============================================================================
extern "C" void kernel_launch(void* const* d_in, const int* in_sizes, int n_in,
                              void* d_out, int out_size) {
    (void)in_sizes; (void)n_in; (void)out_size;
    const float* x = (const float*)d_in[0];
    const float* pb = (const float*)d_in[1];
    const float* Wq_w = (const float*)d_in[2];
    const float* Wkv_w = (const float*)d_in[3];
    const float* Wout_w = (const float*)d_in[4];
    const float* bout_w = (const float*)d_in[5];
    const float* Wq_h = (const float*)d_in[6];
    const float* Wkv_h = (const float*)d_in[7];
    const float* Wout_h = (const float*)d_in[8];
    const float* bout_h = (const float*)d_in[9];
    const float* lng = (const float*)d_in[10];
    const float* lnb = (const float*)d_in[11];
    const float* Wp = (const float*)d_in[12];
    float* out = (float*)d_out;

    const int smw = (4 * 256 * XS + 2 * 64 * XS) * (int)sizeof(__nv_bfloat16);
    const int smp = (64 * 257 + 64 * 68) * (int)sizeof(float);
    const int smd = (64 * 68 + 256 * 68) * (int)sizeof(float);
    const int sma = (256 * 68 * 2 + 64 * 68) * (int)sizeof(float);
    cudaFuncSetAttribute(k_width_mma, cudaFuncAttributeMaxDynamicSharedMemorySize, smw);
    cudaFuncSetAttribute(k_hproj, cudaFuncAttributeMaxDynamicSharedMemorySize, smp);
    cudaFuncSetAttribute(k_hdots, cudaFuncAttributeMaxDynamicSharedMemorySize, smd);
    cudaFuncSetAttribute(k_hav, cudaFuncAttributeMaxDynamicSharedMemorySize, sma);

    k_init<<<16384, 256>>>(bout_w, bout_h, out);
    k_zero_dots<<<2048, 256>>>();
    k_width_mma<<<dim3(256, 8), 512, smw>>>(x, Wq_w, Wkv_w, Wout_w, out);
    k_hproj<<<256, 256, smp>>>(x, Wq_h, Wkv_h);
    k_pair<<<8192, 256>>>(pb, lng, lnb, Wp);
    k_hdots<<<dim3(8, 4, 8), 256, smd>>>();
    k_hsm<<<256, 256>>>();
    k_hav<<<dim3(256, 8), 256, sma>>>(Wout_h, out);
}

// round 7
// speedup vs baseline: 3.0948x; 2.0823x over previous
#include <cuda_runtime.h>
#include <cuda_bf16.h>
#include <cstdint>
#include <math.h>

#define HH 256
#define WW 256
#define DD 64
#define NH 8
#define KBIG 16384
#define XS 72

// bf16 hi/lo scratch (device globals)
__device__ __nv_bfloat16 g_Qh[NH * 256 * KBIG], g_Ql[NH * 256 * KBIG];
__device__ __nv_bfloat16 g_Kh[NH * 256 * KBIG], g_Kl[NH * 256 * KBIG];
__device__ __nv_bfloat16 g_Vh[256 * 256 * 512], g_Vl[256 * 256 * 512];
__device__ __nv_bfloat16 g_Ph[NH * 256 * 256], g_Pl[NH * 256 * 256];
__device__ float g_DOTS[NH * 256 * 256];
__device__ float g_PB[NH * 256 * 256];

// ---------------- warp-MMA helpers ------------------------------------------
__device__ __forceinline__ void ldsm4(uint32_t* r, uint32_t a) {
    asm volatile("ldmatrix.sync.aligned.m8n8.x4.shared.b16 {%0,%1,%2,%3}, [%4];"
                 : "=r"(r[0]), "=r"(r[1]), "=r"(r[2]), "=r"(r[3]) : "r"(a));
}
__device__ __forceinline__ void ldsm4t(uint32_t* r, uint32_t a) {
    asm volatile("ldmatrix.sync.aligned.m8n8.x4.trans.shared.b16 {%0,%1,%2,%3}, [%4];"
                 : "=r"(r[0]), "=r"(r[1]), "=r"(r[2]), "=r"(r[3]) : "r"(a));
}
__device__ __forceinline__ void mma16816(float* c, const uint32_t* a, const uint32_t* b) {
    asm volatile("mma.sync.aligned.m16n8k16.row.col.f32.bf16.bf16.f32 "
                 "{%0,%1,%2,%3},{%4,%5,%6,%7},{%8,%9},{%0,%1,%2,%3};"
                 : "+f"(c[0]), "+f"(c[1]), "+f"(c[2]), "+f"(c[3])
                 : "r"(a[0]), "r"(a[1]), "r"(a[2]), "r"(a[3]), "r"(b[0]), "r"(b[1]));
}
__device__ __forceinline__ void split2(float a, float b, uint32_t& h, uint32_t& l) {
    __nv_bfloat162 hv = __floats2bfloat162_rn(a, b);
    float2 hf = __bfloat1622float2(hv);
    __nv_bfloat162 lv = __floats2bfloat162_rn(a - hf.x, b - hf.y);
    h = *reinterpret_cast<uint32_t*>(&hv);
    l = *reinterpret_cast<uint32_t*>(&lv);
}
__device__ __forceinline__ uint32_t aAddr(const __nv_bfloat16* base, int lane, int r0, int k0) {
    int row = r0 + (lane & 15), col = k0 + ((lane >> 4) << 3);
    return (uint32_t)__cvta_generic_to_shared(base + row * XS + col);
}
__device__ __forceinline__ uint32_t bAddrT(const __nv_bfloat16* base, int lane, int k0, int n0) {
    int row = k0 + (lane & 7) + (((lane >> 3) & 1) << 3);
    int col = n0 + ((lane >> 4) << 3);
    return (uint32_t)__cvta_generic_to_shared(base + row * XS + col);
}
__device__ __forceinline__ uint32_t bAddrN(const __nv_bfloat16* base, int lane, int j0, int d0) {
    int row = j0 + (lane & 7) + ((lane >> 4) << 3);
    int col = d0 + (((lane >> 3) & 1) << 3);
    return (uint32_t)__cvta_generic_to_shared(base + row * XS + col);
}

// ============================================================================
// Width attention (validated round 5) — unchanged.
// ============================================================================
__global__ void __launch_bounds__(512, 1)
k_width_mma(const float* __restrict__ x, const float* __restrict__ Wq,
            const float* __restrict__ Wkv, const float* __restrict__ Wout,
            float* __restrict__ out) {
    extern __shared__ __nv_bfloat16 sb[];
    __nv_bfloat16* Xh = sb;
    __nv_bfloat16* Xl = sb + 256 * XS;
    __nv_bfloat16* Kh = sb + 2 * 256 * XS;
    __nv_bfloat16* Kl = sb + 3 * 256 * XS;
    __nv_bfloat16* Wh = sb + 4 * 256 * XS;
    __nv_bfloat16* Wl = Wh + 64 * XS;

    const int t = threadIdx.x, lane = t & 31, warp = t >> 5, m0 = warp * 16;
    const int w = blockIdx.x, head = blockIdx.y;
    {
        int row = t >> 1, q0 = (t & 1) * 8;
        const float4* src = (const float4*)(x + (size_t)row * (WW * DD) + w * DD) + q0;
#pragma unroll
        for (int q4 = 0; q4 < 8; q4++) {
            float4 v = src[q4];
            uint32_t h0, l0, h1, l1;
            split2(v.x, v.y, h0, l0);
            split2(v.z, v.w, h1, l1);
            int cc = (q0 + q4) * 4;
            *(uint32_t*)(Xh + row * XS + cc) = h0;
            *(uint32_t*)(Xh + row * XS + cc + 2) = h1;
            *(uint32_t*)(Xl + row * XS + cc) = l0;
            *(uint32_t*)(Xl + row * XS + cc + 2) = l1;
        }
    }
    auto loadW = [&](const float* wsrc, int stride, float scale) {
        for (int e = t; e < 2048; e += 512) {
            int k = e >> 5, n2 = e & 31;
            float2 v = *(const float2*)(wsrc + (size_t)k * stride + n2 * 2);
            uint32_t h, l;
            split2(v.x * scale, v.y * scale, h, l);
            *(uint32_t*)(Wh + k * XS + n2 * 2) = h;
            *(uint32_t*)(Wl + k * XS + n2 * 2) = l;
        }
    };
    auto proj = [&](float (&c)[8][4]) {
#pragma unroll
        for (int nt = 0; nt < 8; nt++)
#pragma unroll
            for (int i = 0; i < 4; i++) c[nt][i] = 0.f;
#pragma unroll
        for (int ks = 0; ks < 4; ks++) {
            uint32_t ah[4], al[4];
            ldsm4(ah, aAddr(Xh, lane, m0, ks * 16));
            ldsm4(al, aAddr(Xl, lane, m0, ks * 16));
#pragma unroll
            for (int np = 0; np < 4; np++) {
                uint32_t bh[4], bl[4];
                ldsm4t(bh, bAddrT(Wh, lane, ks * 16, np * 16));
                ldsm4t(bl, bAddrT(Wl, lane, ks * 16, np * 16));
#pragma unroll
                for (int hf = 0; hf < 2; hf++) {
                    float* cc = c[np * 2 + hf];
                    mma16816(cc, ah, bh + hf * 2);
                    mma16816(cc, al, bh + hf * 2);
                    mma16816(cc, ah, bl + hf * 2);
                }
            }
        }
    };
    auto storeC = [&](float (&c)[8][4], __nv_bfloat16* Dh, __nv_bfloat16* Dl) {
#pragma unroll
        for (int nt = 0; nt < 8; nt++) {
            int r = m0 + (lane >> 2), cc = nt * 8 + ((lane & 3) << 1);
            uint32_t h, l;
            split2(c[nt][0], c[nt][1], h, l);
            *(uint32_t*)(Dh + r * XS + cc) = h;
            *(uint32_t*)(Dl + r * XS + cc) = l;
            split2(c[nt][2], c[nt][3], h, l);
            *(uint32_t*)(Dh + (r + 8) * XS + cc) = h;
            *(uint32_t*)(Dl + (r + 8) * XS + cc) = l;
        }
    };

    float c[8][4];
    loadW(Wkv + head * 64, 1024, 1.f);
    __syncthreads();
    proj(c);
    storeC(c, Kh, Kl);
    __syncthreads();
    loadW(Wq + head * 64, 512, 0.125f);
    __syncthreads();
    proj(c);
    uint32_t qh[4][4], ql[4][4];
#pragma unroll
    for (int ks = 0; ks < 4; ks++) {
        split2(c[2 * ks][0], c[2 * ks][1], qh[ks][0], ql[ks][0]);
        split2(c[2 * ks][2], c[2 * ks][3], qh[ks][1], ql[ks][1]);
        split2(c[2 * ks + 1][0], c[2 * ks + 1][1], qh[ks][2], ql[ks][2]);
        split2(c[2 * ks + 1][2], c[2 * ks + 1][3], qh[ks][3], ql[ks][3]);
    }
    __syncthreads();
    loadW(Wkv + 512 + head * 64, 1024, 1.f);
    __syncthreads();
    proj(c);
    storeC(c, Xh, Xl);
    __syncthreads();
    loadW(Wout + (size_t)head * 64 * 64, 64, 1.f);
    __syncthreads();

    float o[8][4];
#pragma unroll
    for (int nt = 0; nt < 8; nt++)
#pragma unroll
        for (int i = 0; i < 4; i++) o[nt][i] = 0.f;
    float lsum[2] = {0.f, 0.f};

    for (int jc = 0; jc < 8; jc++) {
        float s[4][4];
#pragma unroll
        for (int jt = 0; jt < 4; jt++)
#pragma unroll
            for (int i = 0; i < 4; i++) s[jt][i] = 0.f;
#pragma unroll
        for (int ks = 0; ks < 4; ks++) {
            uint32_t kbh[2][4], kbl[2][4];
            ldsm4(kbh[0], bAddrN(Kh, lane, jc * 32, ks * 16));
            ldsm4(kbh[1], bAddrN(Kh, lane, jc * 32 + 16, ks * 16));
            ldsm4(kbl[0], bAddrN(Kl, lane, jc * 32, ks * 16));
            ldsm4(kbl[1], bAddrN(Kl, lane, jc * 32 + 16, ks * 16));
#pragma unroll
            for (int jt = 0; jt < 4; jt++) {
                float* ss = s[jt];
                const uint32_t* bh = &kbh[jt >> 1][(jt & 1) * 2];
                const uint32_t* bl = &kbl[jt >> 1][(jt & 1) * 2];
                mma16816(ss, qh[ks], bh);
                mma16816(ss, ql[ks], bh);
                mma16816(ss, qh[ks], bl);
            }
        }
        uint32_t ph[2][4], pl[2][4];
#pragma unroll
        for (int k2 = 0; k2 < 2; k2++) {
            float e0 = __expf(s[2 * k2][0]), e1 = __expf(s[2 * k2][1]);
            float e2 = __expf(s[2 * k2][2]), e3 = __expf(s[2 * k2][3]);
            float f0 = __expf(s[2 * k2 + 1][0]), f1 = __expf(s[2 * k2 + 1][1]);
            float f2 = __expf(s[2 * k2 + 1][2]), f3 = __expf(s[2 * k2 + 1][3]);
            lsum[0] += e0 + e1 + f0 + f1;
            lsum[1] += e2 + e3 + f2 + f3;
            split2(e0, e1, ph[k2][0], pl[k2][0]);
            split2(e2, e3, ph[k2][1], pl[k2][1]);
            split2(f0, f1, ph[k2][2], pl[k2][2]);
            split2(f2, f3, ph[k2][3], pl[k2][3]);
        }
#pragma unroll
        for (int k2 = 0; k2 < 2; k2++) {
            int j0 = jc * 32 + k2 * 16;
#pragma unroll
            for (int np = 0; np < 4; np++) {
                uint32_t vb[4], vl[4];
                ldsm4t(vb, bAddrT(Xh, lane, j0, np * 16));
                ldsm4t(vl, bAddrT(Xl, lane, j0, np * 16));
#pragma unroll
                for (int hf = 0; hf < 2; hf++) {
                    float* oo = o[np * 2 + hf];
                    mma16816(oo, ph[k2], vb + hf * 2);
                    mma16816(oo, pl[k2], vb + hf * 2);
                    mma16816(oo, ph[k2], vl + hf * 2);
                }
            }
        }
    }
#pragma unroll
    for (int i = 0; i < 2; i++) {
        lsum[i] += __shfl_xor_sync(0xffffffffu, lsum[i], 1);
        lsum[i] += __shfl_xor_sync(0xffffffffu, lsum[i], 2);
    }
    float i0 = 1.f / lsum[0], i1 = 1.f / lsum[1];
    uint32_t oh[4][4], ol[4][4];
#pragma unroll
    for (int ks = 0; ks < 4; ks++) {
        split2(o[2 * ks][0] * i0, o[2 * ks][1] * i0, oh[ks][0], ol[ks][0]);
        split2(o[2 * ks][2] * i1, o[2 * ks][3] * i1, oh[ks][1], ol[ks][1]);
        split2(o[2 * ks + 1][0] * i0, o[2 * ks + 1][1] * i0, oh[ks][2], ol[ks][2]);
        split2(o[2 * ks + 1][2] * i1, o[2 * ks + 1][3] * i1, oh[ks][3], ol[ks][3]);
    }
    float r[8][4];
#pragma unroll
    for (int nt = 0; nt < 8; nt++)
#pragma unroll
        for (int i = 0; i < 4; i++) r[nt][i] = 0.f;
#pragma unroll
    for (int ks = 0; ks < 4; ks++)
#pragma unroll
        for (int np = 0; np < 4; np++) {
            uint32_t bh[4], bl[4];
            ldsm4t(bh, bAddrT(Wh, lane, ks * 16, np * 16));
            ldsm4t(bl, bAddrT(Wl, lane, ks * 16, np * 16));
#pragma unroll
            for (int hf = 0; hf < 2; hf++) {
                float* rr = r[np * 2 + hf];
                mma16816(rr, oh[ks], bh + hf * 2);
                mma16816(rr, ol[ks], bh + hf * 2);
                mma16816(rr, oh[ks], bl + hf * 2);
            }
        }
#pragma unroll
    for (int nt = 0; nt < 8; nt++) {
        int row = m0 + (lane >> 2), col = nt * 8 + ((lane & 3) << 1);
        float* op = out + ((size_t)row * WW + w) * DD;
        atomicAdd(op + col, 0.5f * r[nt][0]);
        atomicAdd(op + col + 1, 0.5f * r[nt][1]);
        float* op2 = out + ((size_t)(row + 8) * WW + w) * DD;
        atomicAdd(op2 + col, 0.5f * r[nt][2]);
        atomicAdd(op2 + col + 1, 0.5f * r[nt][3]);
    }
}

// ============================================================================
// Height projection via MMA: per row r, X[256x64] @ {Wq(1/128),Wk,Wv} chunks.
// ============================================================================
__global__ void __launch_bounds__(512, 1)
k_hproj_mma(const float* __restrict__ x, const float* __restrict__ Wq,
            const float* __restrict__ Wkv) {
    extern __shared__ __nv_bfloat16 sb[];
    __nv_bfloat16* Xh = sb;
    __nv_bfloat16* Xl = sb + 256 * XS;
    __nv_bfloat16* Wh = sb + 2 * 256 * XS;
    __nv_bfloat16* Wl = Wh + 64 * XS;

    const int t = threadIdx.x, lane = t & 31, warp = t >> 5, m0 = warp * 16;
    const int r = blockIdx.x;
    {
        int row = t >> 1, q0 = (t & 1) * 8;
        const float4* src = (const float4*)(x + (size_t)r * (WW * DD) + row * 64) + q0;
#pragma unroll
        for (int q4 = 0; q4 < 8; q4++) {
            float4 v = src[q4];
            uint32_t h0, l0, h1, l1;
            split2(v.x, v.y, h0, l0);
            split2(v.z, v.w, h1, l1);
            int cc = (q0 + q4) * 4;
            *(uint32_t*)(Xh + row * XS + cc) = h0;
            *(uint32_t*)(Xh + row * XS + cc + 2) = h1;
            *(uint32_t*)(Xl + row * XS + cc) = l0;
            *(uint32_t*)(Xl + row * XS + cc + 2) = l1;
        }
    }
    for (int mk = 0; mk < 3; mk++) {
        for (int g = 0; g < 8; g++) {
            const float* wsrc;
            int stride;
            float scale = 1.f;
            if (mk == 0) { wsrc = Wq + g * 64; stride = 512; scale = 0.0078125f; }
            else if (mk == 1) { wsrc = Wkv + g * 64; stride = 1024; }
            else { wsrc = Wkv + 512 + g * 64; stride = 1024; }
            for (int e = t; e < 2048; e += 512) {
                int k = e >> 5, n2 = e & 31;
                float2 v = *(const float2*)(wsrc + (size_t)k * stride + n2 * 2);
                uint32_t h, l;
                split2(v.x * scale, v.y * scale, h, l);
                *(uint32_t*)(Wh + k * XS + n2 * 2) = h;
                *(uint32_t*)(Wl + k * XS + n2 * 2) = l;
            }
            __syncthreads();
            float c[8][4];
#pragma unroll
            for (int nt = 0; nt < 8; nt++)
#pragma unroll
                for (int i = 0; i < 4; i++) c[nt][i] = 0.f;
#pragma unroll
            for (int ks = 0; ks < 4; ks++) {
                uint32_t ah[4], al[4];
                ldsm4(ah, aAddr(Xh, lane, m0, ks * 16));
                ldsm4(al, aAddr(Xl, lane, m0, ks * 16));
#pragma unroll
                for (int np = 0; np < 4; np++) {
                    uint32_t bh[4], bl[4];
                    ldsm4t(bh, bAddrT(Wh, lane, ks * 16, np * 16));
                    ldsm4t(bl, bAddrT(Wl, lane, ks * 16, np * 16));
#pragma unroll
                    for (int hf = 0; hf < 2; hf++) {
                        float* cc = c[np * 2 + hf];
                        mma16816(cc, ah, bh + hf * 2);
                        mma16816(cc, al, bh + hf * 2);
                        mma16816(cc, ah, bl + hf * 2);
                    }
                }
            }
#pragma unroll
            for (int nt = 0; nt < 8; nt++) {
                int row = m0 + (lane >> 2), cc = nt * 8 + ((lane & 3) << 1);
                uint32_t h0, l0, h1, l1;
                split2(c[nt][0], c[nt][1], h0, l0);
                split2(c[nt][2], c[nt][3], h1, l1);
                if (mk < 2) {
                    __nv_bfloat16* dh = (mk == 0) ? g_Qh : g_Kh;
                    __nv_bfloat16* dl = (mk == 0) ? g_Ql : g_Kl;
                    size_t i1 = ((size_t)(g * 256 + row)) * KBIG + r * 64 + cc;
                    size_t i2 = ((size_t)(g * 256 + row + 8)) * KBIG + r * 64 + cc;
                    *(uint32_t*)(dh + i1) = h0;
                    *(uint32_t*)(dl + i1) = l0;
                    *(uint32_t*)(dh + i2) = h1;
                    *(uint32_t*)(dl + i2) = l1;
                } else {
                    size_t i1 = ((size_t)(r * 256 + row)) * 512 + g * 64 + cc;
                    size_t i2 = ((size_t)(r * 256 + row + 8)) * 512 + g * 64 + cc;
                    *(uint32_t*)(g_Vh + i1) = h0;
                    *(uint32_t*)(g_Vl + i1) = l0;
                    *(uint32_t*)(g_Vh + i2) = h1;
                    *(uint32_t*)(g_Vl + i2) = l1;
                }
            }
            __syncthreads();
        }
    }
}

// ============================================================================
// Height dots via MMA: grid (kc=4, it=4, head=8); block 64 i x 256 j, K=4096.
// ============================================================================
__global__ void __launch_bounds__(512, 1) k_hdots_mma() {
    extern __shared__ __nv_bfloat16 sb[];
    __nv_bfloat16* Qh = sb;
    __nv_bfloat16* Ql = sb + 64 * XS;
    __nv_bfloat16* Kh = sb + 2 * 64 * XS;
    __nv_bfloat16* Kl = Kh + 256 * XS;

    const int t = threadIdx.x, lane = t & 31, warp = t >> 5;
    const int kc = blockIdx.x, it = blockIdx.y, head = blockIdx.z;
    const int wm = warp >> 2, wn = warp & 3;
    const int m0 = wm * 16, j0 = wn * 64;

    float c[8][4];
#pragma unroll
    for (int nt = 0; nt < 8; nt++)
#pragma unroll
        for (int i = 0; i < 4; i++) c[nt][i] = 0.f;

    for (int step = 0; step < 64; step++) {
        const int k0 = kc * 4096 + step * 64;
        __syncthreads();
        for (int e = t; e < 2048; e += 512) {
            int row = e >> 5, cp = (e & 31) * 2;
            size_t gi = ((size_t)(head * 256 + it * 64 + row)) * KBIG + k0 + cp;
            *(uint32_t*)(Qh + row * XS + cp) = *(const uint32_t*)(g_Qh + gi);
            *(uint32_t*)(Ql + row * XS + cp) = *(const uint32_t*)(g_Ql + gi);
        }
        for (int e = t; e < 8192; e += 512) {
            int row = e >> 5, cp = (e & 31) * 2;
            size_t gi = ((size_t)(head * 256 + row)) * KBIG + k0 + cp;
            *(uint32_t*)(Kh + row * XS + cp) = *(const uint32_t*)(g_Kh + gi);
            *(uint32_t*)(Kl + row * XS + cp) = *(const uint32_t*)(g_Kl + gi);
        }
        __syncthreads();
#pragma unroll
        for (int ks = 0; ks < 4; ks++) {
            uint32_t ah[4], al[4];
            ldsm4(ah, aAddr(Qh, lane, m0, ks * 16));
            ldsm4(al, aAddr(Ql, lane, m0, ks * 16));
#pragma unroll
            for (int jt = 0; jt < 4; jt++) {
                uint32_t bh[4], bl[4];
                ldsm4(bh, bAddrN(Kh, lane, j0 + jt * 16, ks * 16));
                ldsm4(bl, bAddrN(Kl, lane, j0 + jt * 16, ks * 16));
#pragma unroll
                for (int hf = 0; hf < 2; hf++) {
                    float* cc = c[jt * 2 + hf];
                    mma16816(cc, ah, bh + hf * 2);
                    mma16816(cc, al, bh + hf * 2);
                    mma16816(cc, ah, bl + hf * 2);
                }
            }
        }
    }
#pragma unroll
    for (int nt = 0; nt < 8; nt++) {
        int row = it * 64 + m0 + (lane >> 2), col = j0 + nt * 8 + ((lane & 3) << 1);
        atomicAdd(&g_DOTS[head * 65536 + row * 256 + col], c[nt][0]);
        atomicAdd(&g_DOTS[head * 65536 + row * 256 + col + 1], c[nt][1]);
        atomicAdd(&g_DOTS[head * 65536 + (row + 8) * 256 + col], c[nt][2]);
        atomicAdd(&g_DOTS[head * 65536 + (row + 8) * 256 + col + 1], c[nt][3]);
    }
}

// ============================================================================
// Softmax (+pair bias) -> normalized P as bf16 hi/lo.
// ============================================================================
__global__ void k_hsm2() {
    const int t = threadIdx.x, warp = t >> 5, lane = t & 31;
    const int row = blockIdx.x * 8 + warp;
    float v[8];
    float mx = -1e30f;
#pragma unroll
    for (int kk = 0; kk < 8; kk++) {
        int j = kk * 32 + lane;
        v[kk] = g_DOTS[row * 256 + j] + g_PB[row * 256 + j];
        mx = fmaxf(mx, v[kk]);
    }
#pragma unroll
    for (int o = 16; o; o >>= 1) mx = fmaxf(mx, __shfl_xor_sync(0xffffffffu, mx, o));
    float s = 0.f;
#pragma unroll
    for (int kk = 0; kk < 8; kk++) { v[kk] = __expf(v[kk] - mx); s += v[kk]; }
#pragma unroll
    for (int o = 16; o; o >>= 1) s += __shfl_xor_sync(0xffffffffu, s, o);
    float inv = 1.f / s;
#pragma unroll
    for (int kk = 0; kk < 8; kk++) {
        float p = v[kk] * inv;
        __nv_bfloat16 h = __float2bfloat16_rn(p);
        __nv_bfloat16 l = __float2bfloat16_rn(p - __bfloat162float(h));
        g_Ph[row * 256 + kk * 32 + lane] = h;
        g_Pl[row * 256 + kk * 32 + lane] = l;
    }
}

// ============================================================================
// Height AV + out-projection via MMA: block (r, head); 16 warps x 16 i rows.
// ============================================================================
__global__ void __launch_bounds__(512, 1)
k_hav_mma(const float* __restrict__ Wout, float* __restrict__ out) {
    extern __shared__ __nv_bfloat16 sb[];
    __nv_bfloat16* Ph = sb;
    __nv_bfloat16* Pl = sb + 256 * XS;
    __nv_bfloat16* Vh = sb + 2 * 256 * XS;
    __nv_bfloat16* Vl = Vh + 64 * XS;
    __nv_bfloat16* Wh = Vl + 64 * XS;
    __nv_bfloat16* Wl = Wh + 64 * XS;

    const int t = threadIdx.x, lane = t & 31, warp = t >> 5, m0 = warp * 16;
    const int r = blockIdx.x, head = blockIdx.y;

    for (int e = t; e < 2048; e += 512) {
        int k = e >> 5, n2 = e & 31;
        float2 v = *(const float2*)(Wout + (size_t)(head * 64 + k) * 64 + n2 * 2);
        uint32_t h, l;
        split2(v.x, v.y, h, l);
        *(uint32_t*)(Wh + k * XS + n2 * 2) = h;
        *(uint32_t*)(Wl + k * XS + n2 * 2) = l;
    }

    float o[8][4];
#pragma unroll
    for (int nt = 0; nt < 8; nt++)
#pragma unroll
        for (int i = 0; i < 4; i++) o[nt][i] = 0.f;

    for (int jt = 0; jt < 4; jt++) {
        __syncthreads();
        for (int e = t; e < 8192; e += 512) {
            int row = e >> 5, cp = (e & 31) * 2;
            size_t gi = ((size_t)(head * 256 + row)) * 256 + jt * 64 + cp;
            *(uint32_t*)(Ph + row * XS + cp) = *(const uint32_t*)(g_Ph + gi);
            *(uint32_t*)(Pl + row * XS + cp) = *(const uint32_t*)(g_Pl + gi);
        }
        for (int e = t; e < 2048; e += 512) {
            int row = e >> 5, cp = (e & 31) * 2;
            size_t gi = ((size_t)(r * 256 + jt * 64 + row)) * 512 + head * 64 + cp;
            *(uint32_t*)(Vh + row * XS + cp) = *(const uint32_t*)(g_Vh + gi);
            *(uint32_t*)(Vl + row * XS + cp) = *(const uint32_t*)(g_Vl + gi);
        }
        __syncthreads();
#pragma unroll
        for (int ks = 0; ks < 4; ks++) {
            uint32_t ah[4], al[4];
            ldsm4(ah, aAddr(Ph, lane, m0, ks * 16));
            ldsm4(al, aAddr(Pl, lane, m0, ks * 16));
#pragma unroll
            for (int np = 0; np < 4; np++) {
                uint32_t bh[4], bl[4];
                ldsm4t(bh, bAddrT(Vh, lane, ks * 16, np * 16));
                ldsm4t(bl, bAddrT(Vl, lane, ks * 16, np * 16));
#pragma unroll
                for (int hf = 0; hf < 2; hf++) {
                    float* oo = o[np * 2 + hf];
                    mma16816(oo, ah, bh + hf * 2);
                    mma16816(oo, al, bh + hf * 2);
                    mma16816(oo, ah, bl + hf * 2);
                }
            }
        }
    }
    uint32_t oh[4][4], ol[4][4];
#pragma unroll
    for (int ks = 0; ks < 4; ks++) {
        split2(o[2 * ks][0], o[2 * ks][1], oh[ks][0], ol[ks][0]);
        split2(o[2 * ks][2], o[2 * ks][3], oh[ks][1], ol[ks][1]);
        split2(o[2 * ks + 1][0], o[2 * ks + 1][1], oh[ks][2], ol[ks][2]);
        split2(o[2 * ks + 1][2], o[2 * ks + 1][3], oh[ks][3], ol[ks][3]);
    }
    float rr[8][4];
#pragma unroll
    for (int nt = 0; nt < 8; nt++)
#pragma unroll
        for (int i = 0; i < 4; i++) rr[nt][i] = 0.f;
#pragma unroll
    for (int ks = 0; ks < 4; ks++)
#pragma unroll
        for (int np = 0; np < 4; np++) {
            uint32_t bh[4], bl[4];
            ldsm4t(bh, bAddrT(Wh, lane, ks * 16, np * 16));
            ldsm4t(bl, bAddrT(Wl, lane, ks * 16, np * 16));
#pragma unroll
            for (int hf = 0; hf < 2; hf++) {
                float* cc = rr[np * 2 + hf];
                mma16816(cc, oh[ks], bh + hf * 2);
                mma16816(cc, ol[ks], bh + hf * 2);
                mma16816(cc, oh[ks], bl + hf * 2);
            }
        }
#pragma unroll
    for (int nt = 0; nt < 8; nt++) {
        int row = m0 + (lane >> 2), col = nt * 8 + ((lane & 3) << 1);
        float* op = out + ((size_t)r * WW + row) * DD;
        atomicAdd(op + col, 0.5f * rr[nt][0]);
        atomicAdd(op + col + 1, 0.5f * rr[nt][1]);
        float* op2 = out + ((size_t)r * WW + row + 8) * DD;
        atomicAdd(op2 + col, 0.5f * rr[nt][2]);
        atomicAdd(op2 + col + 1, 0.5f * rr[nt][3]);
    }
}

// ============================ small kernels ==================================
__global__ void k_init(const float* __restrict__ bw, const float* __restrict__ bh,
                       float* __restrict__ out) {
    int idx = blockIdx.x * 256 + threadIdx.x;
    out[idx] = 0.5f * (bw[idx & 63] + bh[idx & 63]);
}
__global__ void k_zero_dots() { g_DOTS[blockIdx.x * 256 + threadIdx.x] = 0.f; }

__global__ void k_pair(const float* __restrict__ pb, const float* __restrict__ g,
                       const float* __restrict__ b, const float* __restrict__ Wp) {
    __shared__ float swp[1024], sg[128], sb2[128];
    const int t = threadIdx.x;
    if (t < 128) { sg[t] = g[t]; sb2[t] = b[t]; }
    for (int e = t; e < 1024; e += 256) swp[e] = Wp[e];
    __syncthreads();
    const int warp = t >> 5, lane = t & 31;
    const int gw = blockIdx.x * 8 + warp;
    const int i = gw >> 8, j = gw & 255;
    const float4* src = (const float4*)(pb + (size_t)gw * 128);
    float4 v = src[lane];
    float s1 = v.x + v.y + v.z + v.w;
    float s2 = v.x * v.x + v.y * v.y + v.z * v.z + v.w * v.w;
#pragma unroll
    for (int o = 16; o; o >>= 1) {
        s1 += __shfl_xor_sync(0xffffffffu, s1, o);
        s2 += __shfl_xor_sync(0xffffffffu, s2, o);
    }
    float mu = s1 * (1.f / 128.f);
    float rstd = rsqrtf(s2 * (1.f / 128.f) - mu * mu + 1e-5f);
    float phd[8];
#pragma unroll
    for (int h = 0; h < 8; h++) phd[h] = 0.f;
    float vv[4] = {v.x, v.y, v.z, v.w};
#pragma unroll
    for (int qi = 0; qi < 4; qi++) {
        int p = lane * 4 + qi;
        float n = (vv[qi] - mu) * rstd * sg[p] + sb2[p];
#pragma unroll
        for (int h = 0; h < 8; h++) phd[h] = fmaf(n, swp[p * 8 + h], phd[h]);
    }
#pragma unroll
    for (int h = 0; h < 8; h++)
#pragma unroll
        for (int o = 16; o; o >>= 1) phd[h] += __shfl_xor_sync(0xffffffffu, phd[h], o);
    if (lane == 0)
#pragma unroll
        for (int h = 0; h < 8; h++) g_PB[h * 65536 + i * 256 + j] = phd[h];
}

// ============================================================================
extern "C" void kernel_launch(void* const* d_in, const int* in_sizes, int n_in,
                              void* d_out, int out_size) {
    (void)in_sizes; (void)n_in; (void)out_size;
    const float* x = (const float*)d_in[0];
    const float* pb = (const float*)d_in[1];
    const float* Wq_w = (const float*)d_in[2];
    const float* Wkv_w = (const float*)d_in[3];
    const float* Wout_w = (const float*)d_in[4];
    const float* bout_w = (const float*)d_in[5];
    const float* Wq_h = (const float*)d_in[6];
    const float* Wkv_h = (const float*)d_in[7];
    const float* Wout_h = (const float*)d_in[8];
    const float* bout_h = (const float*)d_in[9];
    const float* lng = (const float*)d_in[10];
    const float* lnb = (const float*)d_in[11];
    const float* Wp = (const float*)d_in[12];
    float* out = (float*)d_out;

    const int smw = (4 * 256 * XS + 2 * 64 * XS) * 2;
    const int smp = (2 * 256 * XS + 2 * 64 * XS) * 2;
    const int smd = (2 * 64 * XS + 2 * 256 * XS) * 2;
    const int sma = (2 * 256 * XS + 4 * 64 * XS) * 2;
    cudaFuncSetAttribute(k_width_mma, cudaFuncAttributeMaxDynamicSharedMemorySize, smw);
    cudaFuncSetAttribute(k_hproj_mma, cudaFuncAttributeMaxDynamicSharedMemorySize, smp);
    cudaFuncSetAttribute(k_hdots_mma, cudaFuncAttributeMaxDynamicSharedMemorySize, smd);
    cudaFuncSetAttribute(k_hav_mma, cudaFuncAttributeMaxDynamicSharedMemorySize, sma);

    k_init<<<16384, 256>>>(bout_w, bout_h, out);  // FULL 4M-element coverage
    k_zero_dots<<<2048, 256>>>();
    k_hproj_mma<<<256, 512, smp>>>(x, Wq_h, Wkv_h);
    k_pair<<<8192, 256>>>(pb, lng, lnb, Wp);
    k_hdots_mma<<<dim3(4, 4, 8), 512, smd>>>();
    k_hsm2<<<256, 256>>>();
    k_hav_mma<<<dim3(256, 8), 512, sma>>>(Wout_h, out);
    k_width_mma<<<dim3(256, 8), 512, smw>>>(x, Wq_w, Wkv_w, Wout_w, out);
}

// round 8
// speedup vs baseline: 3.7748x; 1.2197x over previous
#include <cuda_runtime.h>
#include <cuda_fp16.h>
#include <cstdint>
#include <math.h>

#define HH 256
#define WW 256
#define DD 64
#define NH 8
#define KBIG 16384
#define XS 72

// fp16 scratch: Q needs hi+lo (A operand); K, V hi only (B operands); P hi+lo (A).
__device__ __half g_Qh[NH * 256 * KBIG], g_Ql[NH * 256 * KBIG];
__device__ __half g_Kh[NH * 256 * KBIG];
__device__ __half g_Vh[256 * 256 * 512];
__device__ __half g_Ph[NH * 256 * 256], g_Pl[NH * 256 * 256];
__device__ float g_DOTS[NH * 256 * 256];
__device__ float g_PB[NH * 256 * 256];

// ---------------- warp-MMA helpers ------------------------------------------
__device__ __forceinline__ void ldsm4(uint32_t* r, uint32_t a) {
    asm volatile("ldmatrix.sync.aligned.m8n8.x4.shared.b16 {%0,%1,%2,%3}, [%4];"
                 : "=r"(r[0]), "=r"(r[1]), "=r"(r[2]), "=r"(r[3]) : "r"(a));
}
__device__ __forceinline__ void ldsm4t(uint32_t* r, uint32_t a) {
    asm volatile("ldmatrix.sync.aligned.m8n8.x4.trans.shared.b16 {%0,%1,%2,%3}, [%4];"
                 : "=r"(r[0]), "=r"(r[1]), "=r"(r[2]), "=r"(r[3]) : "r"(a));
}
__device__ __forceinline__ void mmaH(float* c, const uint32_t* a, const uint32_t* b) {
    asm volatile("mma.sync.aligned.m16n8k16.row.col.f32.f16.f16.f32 "
                 "{%0,%1,%2,%3},{%4,%5,%6,%7},{%8,%9},{%0,%1,%2,%3};"
                 : "+f"(c[0]), "+f"(c[1]), "+f"(c[2]), "+f"(c[3])
                 : "r"(a[0]), "r"(a[1]), "r"(a[2]), "r"(a[3]), "r"(b[0]), "r"(b[1]));
}
__device__ __forceinline__ void splitH(float a, float b, uint32_t& h, uint32_t& l) {
    __half2 hv = __floats2half2_rn(a, b);
    float2 hf = __half22float2(hv);
    __half2 lv = __floats2half2_rn(a - hf.x, b - hf.y);
    h = *reinterpret_cast<uint32_t*>(&hv);
    l = *reinterpret_cast<uint32_t*>(&lv);
}
__device__ __forceinline__ uint32_t packH(float a, float b) {
    __half2 hv = __floats2half2_rn(a, b);
    return *reinterpret_cast<uint32_t*>(&hv);
}
__device__ __forceinline__ uint32_t aAddr(const __half* base, int lane, int r0, int k0) {
    int row = r0 + (lane & 15), col = k0 + ((lane >> 4) << 3);
    return (uint32_t)__cvta_generic_to_shared(base + row * XS + col);
}
__device__ __forceinline__ uint32_t bAddrT(const __half* base, int lane, int k0, int n0) {
    int row = k0 + (lane & 7) + (((lane >> 3) & 1) << 3);
    int col = n0 + ((lane >> 4) << 3);
    return (uint32_t)__cvta_generic_to_shared(base + row * XS + col);
}
__device__ __forceinline__ uint32_t bAddrN(const __half* base, int lane, int j0, int d0) {
    int row = j0 + (lane & 7) + ((lane >> 4) << 3);
    int col = d0 + (((lane >> 3) & 1) << 3);
    return (uint32_t)__cvta_generic_to_shared(base + row * XS + col);
}

// ============================================================================
// Width attention, fp16 split-2. Block=(w,head), 16 warps x 16 rows.
// smem: Xh,Xl,Kh (256xXS each; V-hi reuses Xh), Wh (64xXS)  ~117KB
// ============================================================================
__global__ void __launch_bounds__(512, 1)
k_width_mma(const float* __restrict__ x, const float* __restrict__ Wq,
            const float* __restrict__ Wkv, const float* __restrict__ Wout,
            float* __restrict__ out) {
    extern __shared__ __half sb[];
    __half* Xh = sb;                  // later: V hi
    __half* Xl = sb + 256 * XS;
    __half* Kh = sb + 512 * XS;
    __half* Wh = sb + 768 * XS;

    const int t = threadIdx.x, lane = t & 31, warp = t >> 5, m0 = warp * 16;
    const int w = blockIdx.x, head = blockIdx.y;
    {
        int row = t >> 1, q0 = (t & 1) * 8;
        const float4* src = (const float4*)(x + (size_t)row * (WW * DD) + w * DD) + q0;
#pragma unroll
        for (int q4 = 0; q4 < 8; q4++) {
            float4 v = src[q4];
            uint32_t h0, l0, h1, l1;
            splitH(v.x, v.y, h0, l0);
            splitH(v.z, v.w, h1, l1);
            int cc = (q0 + q4) * 4;
            *(uint32_t*)(Xh + row * XS + cc) = h0;
            *(uint32_t*)(Xh + row * XS + cc + 2) = h1;
            *(uint32_t*)(Xl + row * XS + cc) = l0;
            *(uint32_t*)(Xl + row * XS + cc + 2) = l1;
        }
    }
    auto loadW = [&](const float* wsrc, int stride, float scale) {
        for (int e = t; e < 2048; e += 512) {
            int k = e >> 5, n2 = e & 31;
            float2 v = *(const float2*)(wsrc + (size_t)k * stride + n2 * 2);
            *(uint32_t*)(Wh + k * XS + n2 * 2) = packH(v.x * scale, v.y * scale);
        }
    };
    // C[16x64] = X[own 16 rows] @ W  (split-2: ah*bh + al*bh)
    auto proj = [&](float (&c)[8][4]) {
#pragma unroll
        for (int nt = 0; nt < 8; nt++)
#pragma unroll
            for (int i = 0; i < 4; i++) c[nt][i] = 0.f;
#pragma unroll
        for (int ks = 0; ks < 4; ks++) {
            uint32_t ah[4], al[4];
            ldsm4(ah, aAddr(Xh, lane, m0, ks * 16));
            ldsm4(al, aAddr(Xl, lane, m0, ks * 16));
#pragma unroll
            for (int np = 0; np < 4; np++) {
                uint32_t bh[4];
                ldsm4t(bh, bAddrT(Wh, lane, ks * 16, np * 16));
#pragma unroll
                for (int hf = 0; hf < 2; hf++) {
                    float* cc = c[np * 2 + hf];
                    mmaH(cc, ah, bh + hf * 2);
                    mmaH(cc, al, bh + hf * 2);
                }
            }
        }
    };
    auto storeHi = [&](float (&c)[8][4], __half* Dh) {
#pragma unroll
        for (int nt = 0; nt < 8; nt++) {
            int r = m0 + (lane >> 2), cc = nt * 8 + ((lane & 3) << 1);
            *(uint32_t*)(Dh + r * XS + cc) = packH(c[nt][0], c[nt][1]);
            *(uint32_t*)(Dh + (r + 8) * XS + cc) = packH(c[nt][2], c[nt][3]);
        }
    };

    float c[8][4];
    loadW(Wkv + head * 64, 1024, 1.f);  // Wk
    __syncthreads();
    proj(c);
    storeHi(c, Kh);
    __syncthreads();
    loadW(Wq + head * 64, 512, 0.125f);  // Wq (scale folded)
    __syncthreads();
    proj(c);
    uint32_t qh[4][4], ql[4][4];
#pragma unroll
    for (int ks = 0; ks < 4; ks++) {
        splitH(c[2 * ks][0], c[2 * ks][1], qh[ks][0], ql[ks][0]);
        splitH(c[2 * ks][2], c[2 * ks][3], qh[ks][1], ql[ks][1]);
        splitH(c[2 * ks + 1][0], c[2 * ks + 1][1], qh[ks][2], ql[ks][2]);
        splitH(c[2 * ks + 1][2], c[2 * ks + 1][3], qh[ks][3], ql[ks][3]);
    }
    __syncthreads();
    loadW(Wkv + 512 + head * 64, 1024, 1.f);  // Wv
    __syncthreads();
    proj(c);
    storeHi(c, Xh);  // V-hi overwrites X-hi (own rows only)
    __syncthreads();
    loadW(Wout + (size_t)head * 64 * 64, 64, 1.f);  // Wout slice
    __syncthreads();

    float o[8][4];
#pragma unroll
    for (int nt = 0; nt < 8; nt++)
#pragma unroll
        for (int i = 0; i < 4; i++) o[nt][i] = 0.f;
    float lsum[2] = {0.f, 0.f};

    for (int jc = 0; jc < 8; jc++) {
        float s[4][4];
#pragma unroll
        for (int jt = 0; jt < 4; jt++)
#pragma unroll
            for (int i = 0; i < 4; i++) s[jt][i] = 0.f;
#pragma unroll
        for (int ks = 0; ks < 4; ks++) {
            uint32_t kb[2][4];
            ldsm4(kb[0], bAddrN(Kh, lane, jc * 32, ks * 16));
            ldsm4(kb[1], bAddrN(Kh, lane, jc * 32 + 16, ks * 16));
#pragma unroll
            for (int jt = 0; jt < 4; jt++) {
                float* ss = s[jt];
                const uint32_t* bh = &kb[jt >> 1][(jt & 1) * 2];
                mmaH(ss, qh[ks], bh);
                mmaH(ss, ql[ks], bh);
            }
        }
        uint32_t ph[2][4], pl[2][4];
#pragma unroll
        for (int k2 = 0; k2 < 2; k2++) {
            float e0 = __expf(s[2 * k2][0]), e1 = __expf(s[2 * k2][1]);
            float e2 = __expf(s[2 * k2][2]), e3 = __expf(s[2 * k2][3]);
            float f0 = __expf(s[2 * k2 + 1][0]), f1 = __expf(s[2 * k2 + 1][1]);
            float f2 = __expf(s[2 * k2 + 1][2]), f3 = __expf(s[2 * k2 + 1][3]);
            lsum[0] += e0 + e1 + f0 + f1;
            lsum[1] += e2 + e3 + f2 + f3;
            splitH(e0, e1, ph[k2][0], pl[k2][0]);
            splitH(e2, e3, ph[k2][1], pl[k2][1]);
            splitH(f0, f1, ph[k2][2], pl[k2][2]);
            splitH(f2, f3, ph[k2][3], pl[k2][3]);
        }
#pragma unroll
        for (int k2 = 0; k2 < 2; k2++) {
            int j0 = jc * 32 + k2 * 16;
#pragma unroll
            for (int np = 0; np < 4; np++) {
                uint32_t vb[4];
                ldsm4t(vb, bAddrT(Xh, lane, j0, np * 16));
#pragma unroll
                for (int hf = 0; hf < 2; hf++) {
                    float* oo = o[np * 2 + hf];
                    mmaH(oo, ph[k2], vb + hf * 2);
                    mmaH(oo, pl[k2], vb + hf * 2);
                }
            }
        }
    }
#pragma unroll
    for (int i = 0; i < 2; i++) {
        lsum[i] += __shfl_xor_sync(0xffffffffu, lsum[i], 1);
        lsum[i] += __shfl_xor_sync(0xffffffffu, lsum[i], 2);
    }
    float i0 = 1.f / lsum[0], i1 = 1.f / lsum[1];
    uint32_t oh[4][4], ol[4][4];
#pragma unroll
    for (int ks = 0; ks < 4; ks++) {
        splitH(o[2 * ks][0] * i0, o[2 * ks][1] * i0, oh[ks][0], ol[ks][0]);
        splitH(o[2 * ks][2] * i1, o[2 * ks][3] * i1, oh[ks][1], ol[ks][1]);
        splitH(o[2 * ks + 1][0] * i0, o[2 * ks + 1][1] * i0, oh[ks][2], ol[ks][2]);
        splitH(o[2 * ks + 1][2] * i1, o[2 * ks + 1][3] * i1, oh[ks][3], ol[ks][3]);
    }
    float r[8][4];
#pragma unroll
    for (int nt = 0; nt < 8; nt++)
#pragma unroll
        for (int i = 0; i < 4; i++) r[nt][i] = 0.f;
#pragma unroll
    for (int ks = 0; ks < 4; ks++)
#pragma unroll
        for (int np = 0; np < 4; np++) {
            uint32_t bh[4];
            ldsm4t(bh, bAddrT(Wh, lane, ks * 16, np * 16));
#pragma unroll
            for (int hf = 0; hf < 2; hf++) {
                float* rr = r[np * 2 + hf];
                mmaH(rr, oh[ks], bh + hf * 2);
                mmaH(rr, ol[ks], bh + hf * 2);
            }
        }
#pragma unroll
    for (int nt = 0; nt < 8; nt++) {
        int row = m0 + (lane >> 2), col = nt * 8 + ((lane & 3) << 1);
        float* op = out + ((size_t)row * WW + w) * DD;
        atomicAdd(op + col, 0.5f * r[nt][0]);
        atomicAdd(op + col + 1, 0.5f * r[nt][1]);
        float* op2 = out + ((size_t)(row + 8) * WW + w) * DD;
        atomicAdd(op2 + col, 0.5f * r[nt][2]);
        atomicAdd(op2 + col + 1, 0.5f * r[nt][3]);
    }
}

// ============================================================================
// Height projection: per row r; Q -> hi+lo, K,V -> hi only.
// ============================================================================
__global__ void __launch_bounds__(512, 1)
k_hproj_mma(const float* __restrict__ x, const float* __restrict__ Wq,
            const float* __restrict__ Wkv) {
    extern __shared__ __half sb[];
    __half* Xh = sb;
    __half* Xl = sb + 256 * XS;
    __half* Wh = sb + 512 * XS;

    const int t = threadIdx.x, lane = t & 31, warp = t >> 5, m0 = warp * 16;
    const int r = blockIdx.x;
    {
        int row = t >> 1, q0 = (t & 1) * 8;
        const float4* src = (const float4*)(x + (size_t)r * (WW * DD) + row * 64) + q0;
#pragma unroll
        for (int q4 = 0; q4 < 8; q4++) {
            float4 v = src[q4];
            uint32_t h0, l0, h1, l1;
            splitH(v.x, v.y, h0, l0);
            splitH(v.z, v.w, h1, l1);
            int cc = (q0 + q4) * 4;
            *(uint32_t*)(Xh + row * XS + cc) = h0;
            *(uint32_t*)(Xh + row * XS + cc + 2) = h1;
            *(uint32_t*)(Xl + row * XS + cc) = l0;
            *(uint32_t*)(Xl + row * XS + cc + 2) = l1;
        }
    }
    for (int mk = 0; mk < 3; mk++) {
        for (int g = 0; g < 8; g++) {
            const float* wsrc;
            int stride;
            float scale = 1.f;
            if (mk == 0) { wsrc = Wq + g * 64; stride = 512; scale = 0.0078125f; }
            else if (mk == 1) { wsrc = Wkv + g * 64; stride = 1024; }
            else { wsrc = Wkv + 512 + g * 64; stride = 1024; }
            for (int e = t; e < 2048; e += 512) {
                int k = e >> 5, n2 = e & 31;
                float2 v = *(const float2*)(wsrc + (size_t)k * stride + n2 * 2);
                *(uint32_t*)(Wh + k * XS + n2 * 2) = packH(v.x * scale, v.y * scale);
            }
            __syncthreads();
            float c[8][4];
#pragma unroll
            for (int nt = 0; nt < 8; nt++)
#pragma unroll
                for (int i = 0; i < 4; i++) c[nt][i] = 0.f;
#pragma unroll
            for (int ks = 0; ks < 4; ks++) {
                uint32_t ah[4], al[4];
                ldsm4(ah, aAddr(Xh, lane, m0, ks * 16));
                ldsm4(al, aAddr(Xl, lane, m0, ks * 16));
#pragma unroll
                for (int np = 0; np < 4; np++) {
                    uint32_t bh[4];
                    ldsm4t(bh, bAddrT(Wh, lane, ks * 16, np * 16));
#pragma unroll
                    for (int hf = 0; hf < 2; hf++) {
                        float* cc = c[np * 2 + hf];
                        mmaH(cc, ah, bh + hf * 2);
                        mmaH(cc, al, bh + hf * 2);
                    }
                }
            }
#pragma unroll
            for (int nt = 0; nt < 8; nt++) {
                int row = m0 + (lane >> 2), cc = nt * 8 + ((lane & 3) << 1);
                if (mk == 0) {  // Q: hi + lo
                    uint32_t h0, l0, h1, l1;
                    splitH(c[nt][0], c[nt][1], h0, l0);
                    splitH(c[nt][2], c[nt][3], h1, l1);
                    size_t i1 = ((size_t)(g * 256 + row)) * KBIG + r * 64 + cc;
                    size_t i2 = ((size_t)(g * 256 + row + 8)) * KBIG + r * 64 + cc;
                    *(uint32_t*)(g_Qh + i1) = h0;
                    *(uint32_t*)(g_Ql + i1) = l0;
                    *(uint32_t*)(g_Qh + i2) = h1;
                    *(uint32_t*)(g_Ql + i2) = l1;
                } else if (mk == 1) {  // K: hi only
                    size_t i1 = ((size_t)(g * 256 + row)) * KBIG + r * 64 + cc;
                    size_t i2 = ((size_t)(g * 256 + row + 8)) * KBIG + r * 64 + cc;
                    *(uint32_t*)(g_Kh + i1) = packH(c[nt][0], c[nt][1]);
                    *(uint32_t*)(g_Kh + i2) = packH(c[nt][2], c[nt][3]);
                } else {  // V: hi only
                    size_t i1 = ((size_t)(r * 256 + row)) * 512 + g * 64 + cc;
                    size_t i2 = ((size_t)(r * 256 + row + 8)) * 512 + g * 64 + cc;
                    *(uint32_t*)(g_Vh + i1) = packH(c[nt][0], c[nt][1]);
                    *(uint32_t*)(g_Vh + i2) = packH(c[nt][2], c[nt][3]);
                }
            }
            __syncthreads();
        }
    }
}

// ============================================================================
// Height dots: grid (kc=4, it=4, head=8); block 64 i x 256 j, K=4096.
// ============================================================================
__global__ void __launch_bounds__(512, 1) k_hdots_mma() {
    extern __shared__ __half sb[];
    __half* Qh = sb;
    __half* Ql = sb + 64 * XS;
    __half* Kh = sb + 128 * XS;

    const int t = threadIdx.x, lane = t & 31, warp = t >> 5;
    const int kc = blockIdx.x, it = blockIdx.y, head = blockIdx.z;
    const int wm = warp >> 2, wn = warp & 3;
    const int m0 = wm * 16, j0 = wn * 64;

    float c[8][4];
#pragma unroll
    for (int nt = 0; nt < 8; nt++)
#pragma unroll
        for (int i = 0; i < 4; i++) c[nt][i] = 0.f;

    for (int step = 0; step < 64; step++) {
        const int k0 = kc * 4096 + step * 64;
        __syncthreads();
        for (int e = t; e < 2048; e += 512) {
            int row = e >> 5, cp = (e & 31) * 2;
            size_t gi = ((size_t)(head * 256 + it * 64 + row)) * KBIG + k0 + cp;
            *(uint32_t*)(Qh + row * XS + cp) = *(const uint32_t*)(g_Qh + gi);
            *(uint32_t*)(Ql + row * XS + cp) = *(const uint32_t*)(g_Ql + gi);
        }
        for (int e = t; e < 8192; e += 512) {
            int row = e >> 5, cp = (e & 31) * 2;
            size_t gi = ((size_t)(head * 256 + row)) * KBIG + k0 + cp;
            *(uint32_t*)(Kh + row * XS + cp) = *(const uint32_t*)(g_Kh + gi);
        }
        __syncthreads();
#pragma unroll
        for (int ks = 0; ks < 4; ks++) {
            uint32_t ah[4], al[4];
            ldsm4(ah, aAddr(Qh, lane, m0, ks * 16));
            ldsm4(al, aAddr(Ql, lane, m0, ks * 16));
#pragma unroll
            for (int jt = 0; jt < 4; jt++) {
                uint32_t bh[4];
                ldsm4(bh, bAddrN(Kh, lane, j0 + jt * 16, ks * 16));
#pragma unroll
                for (int hf = 0; hf < 2; hf++) {
                    float* cc = c[jt * 2 + hf];
                    mmaH(cc, ah, bh + hf * 2);
                    mmaH(cc, al, bh + hf * 2);
                }
            }
        }
    }
#pragma unroll
    for (int nt = 0; nt < 8; nt++) {
        int row = it * 64 + m0 + (lane >> 2), col = j0 + nt * 8 + ((lane & 3) << 1);
        atomicAdd(&g_DOTS[head * 65536 + row * 256 + col], c[nt][0]);
        atomicAdd(&g_DOTS[head * 65536 + row * 256 + col + 1], c[nt][1]);
        atomicAdd(&g_DOTS[head * 65536 + (row + 8) * 256 + col], c[nt][2]);
        atomicAdd(&g_DOTS[head * 65536 + (row + 8) * 256 + col + 1], c[nt][3]);
    }
}

// ============================================================================
// Softmax (+pair bias) -> normalized P as fp16 hi/lo.
// ============================================================================
__global__ void k_hsm2() {
    const int t = threadIdx.x, warp = t >> 5, lane = t & 31;
    const int row = blockIdx.x * 8 + warp;
    float v[8];
    float mx = -1e30f;
#pragma unroll
    for (int kk = 0; kk < 8; kk++) {
        int j = kk * 32 + lane;
        v[kk] = g_DOTS[row * 256 + j] + g_PB[row * 256 + j];
        mx = fmaxf(mx, v[kk]);
    }
#pragma unroll
    for (int o = 16; o; o >>= 1) mx = fmaxf(mx, __shfl_xor_sync(0xffffffffu, mx, o));
    float s = 0.f;
#pragma unroll
    for (int kk = 0; kk < 8; kk++) { v[kk] = __expf(v[kk] - mx); s += v[kk]; }
#pragma unroll
    for (int o = 16; o; o >>= 1) s += __shfl_xor_sync(0xffffffffu, s, o);
    float inv = 1.f / s;
#pragma unroll
    for (int kk = 0; kk < 8; kk++) {
        float p = v[kk] * inv;
        __half h = __float2half_rn(p);
        g_Ph[row * 256 + kk * 32 + lane] = h;
        g_Pl[row * 256 + kk * 32 + lane] = __float2half_rn(p - __half2float(h));
    }
}

// ============================================================================
// Height AV + out-projection: block (r, head); 16 warps x 16 i rows.
// ============================================================================
__global__ void __launch_bounds__(512, 1)
k_hav_mma(const float* __restrict__ Wout, float* __restrict__ out) {
    extern __shared__ __half sb[];
    __half* Ph = sb;
    __half* Pl = sb + 256 * XS;
    __half* Vh = sb + 512 * XS;
    __half* Wh = sb + 576 * XS;

    const int t = threadIdx.x, lane = t & 31, warp = t >> 5, m0 = warp * 16;
    const int r = blockIdx.x, head = blockIdx.y;

    for (int e = t; e < 2048; e += 512) {
        int k = e >> 5, n2 = e & 31;
        float2 v = *(const float2*)(Wout + (size_t)(head * 64 + k) * 64 + n2 * 2);
        *(uint32_t*)(Wh + k * XS + n2 * 2) = packH(v.x, v.y);
    }

    float o[8][4];
#pragma unroll
    for (int nt = 0; nt < 8; nt++)
#pragma unroll
        for (int i = 0; i < 4; i++) o[nt][i] = 0.f;

    for (int jt = 0; jt < 4; jt++) {
        __syncthreads();
        for (int e = t; e < 8192; e += 512) {
            int row = e >> 5, cp = (e & 31) * 2;
            size_t gi = ((size_t)(head * 256 + row)) * 256 + jt * 64 + cp;
            *(uint32_t*)(Ph + row * XS + cp) = *(const uint32_t*)(g_Ph + gi);
            *(uint32_t*)(Pl + row * XS + cp) = *(const uint32_t*)(g_Pl + gi);
        }
        for (int e = t; e < 2048; e += 512) {
            int row = e >> 5, cp = (e & 31) * 2;
            size_t gi = ((size_t)(r * 256 + jt * 64 + row)) * 512 + head * 64 + cp;
            *(uint32_t*)(Vh + row * XS + cp) = *(const uint32_t*)(g_Vh + gi);
        }
        __syncthreads();
#pragma unroll
        for (int ks = 0; ks < 4; ks++) {
            uint32_t ah[4], al[4];
            ldsm4(ah, aAddr(Ph, lane, m0, ks * 16));
            ldsm4(al, aAddr(Pl, lane, m0, ks * 16));
#pragma unroll
            for (int np = 0; np < 4; np++) {
                uint32_t bh[4];
                ldsm4t(bh, bAddrT(Vh, lane, ks * 16, np * 16));
#pragma unroll
                for (int hf = 0; hf < 2; hf++) {
                    float* oo = o[np * 2 + hf];
                    mmaH(oo, ah, bh + hf * 2);
                    mmaH(oo, al, bh + hf * 2);
                }
            }
        }
    }
    uint32_t oh[4][4], ol[4][4];
#pragma unroll
    for (int ks = 0; ks < 4; ks++) {
        splitH(o[2 * ks][0], o[2 * ks][1], oh[ks][0], ol[ks][0]);
        splitH(o[2 * ks][2], o[2 * ks][3], oh[ks][1], ol[ks][1]);
        splitH(o[2 * ks + 1][0], o[2 * ks + 1][1], oh[ks][2], ol[ks][2]);
        splitH(o[2 * ks + 1][2], o[2 * ks + 1][3], oh[ks][3], ol[ks][3]);
    }
    float rr[8][4];
#pragma unroll
    for (int nt = 0; nt < 8; nt++)
#pragma unroll
        for (int i = 0; i < 4; i++) rr[nt][i] = 0.f;
#pragma unroll
    for (int ks = 0; ks < 4; ks++)
#pragma unroll
        for (int np = 0; np < 4; np++) {
            uint32_t bh[4];
            ldsm4t(bh, bAddrT(Wh, lane, ks * 16, np * 16));
#pragma unroll
            for (int hf = 0; hf < 2; hf++) {
                float* cc = rr[np * 2 + hf];
                mmaH(cc, oh[ks], bh + hf * 2);
                mmaH(cc, ol[ks], bh + hf * 2);
            }
        }
#pragma unroll
    for (int nt = 0; nt < 8; nt++) {
        int row = m0 + (lane >> 2), col = nt * 8 + ((lane & 3) << 1);
        float* op = out + ((size_t)r * WW + row) * DD;
        atomicAdd(op + col, 0.5f * rr[nt][0]);
        atomicAdd(op + col + 1, 0.5f * rr[nt][1]);
        float* op2 = out + ((size_t)r * WW + row + 8) * DD;
        atomicAdd(op2 + col, 0.5f * rr[nt][2]);
        atomicAdd(op2 + col + 1, 0.5f * rr[nt][3]);
    }
}

// ============================ small kernels ==================================
__global__ void k_init(const float* __restrict__ bw, const float* __restrict__ bh,
                       float* __restrict__ out) {
    int idx = blockIdx.x * 256 + threadIdx.x;
    out[idx] = 0.5f * (bw[idx & 63] + bh[idx & 63]);
}
__global__ void k_zero_dots() { g_DOTS[blockIdx.x * 256 + threadIdx.x] = 0.f; }

__global__ void k_pair(const float* __restrict__ pb, const float* __restrict__ g,
                       const float* __restrict__ b, const float* __restrict__ Wp) {
    __shared__ float swp[1024], sg[128], sb2[128];
    const int t = threadIdx.x;
    if (t < 128) { sg[t] = g[t]; sb2[t] = b[t]; }
    for (int e = t; e < 1024; e += 256) swp[e] = Wp[e];
    __syncthreads();
    const int warp = t >> 5, lane = t & 31;
    const int gw = blockIdx.x * 8 + warp;
    const int i = gw >> 8, j = gw & 255;
    const float4* src = (const float4*)(pb + (size_t)gw * 128);
    float4 v = src[lane];
    float s1 = v.x + v.y + v.z + v.w;
    float s2 = v.x * v.x + v.y * v.y + v.z * v.z + v.w * v.w;
#pragma unroll
    for (int o = 16; o; o >>= 1) {
        s1 += __shfl_xor_sync(0xffffffffu, s1, o);
        s2 += __shfl_xor_sync(0xffffffffu, s2, o);
    }
    float mu = s1 * (1.f / 128.f);
    float rstd = rsqrtf(s2 * (1.f / 128.f) - mu * mu + 1e-5f);
    float phd[8];
#pragma unroll
    for (int h = 0; h < 8; h++) phd[h] = 0.f;
    float vv[4] = {v.x, v.y, v.z, v.w};
#pragma unroll
    for (int qi = 0; qi < 4; qi++) {
        int p = lane * 4 + qi;
        float n = (vv[qi] - mu) * rstd * sg[p] + sb2[p];
#pragma unroll
        for (int h = 0; h < 8; h++) phd[h] = fmaf(n, swp[p * 8 + h], phd[h]);
    }
#pragma unroll
    for (int h = 0; h < 8; h++)
#pragma unroll
        for (int o = 16; o; o >>= 1) phd[h] += __shfl_xor_sync(0xffffffffu, phd[h], o);
    if (lane == 0)
#pragma unroll
        for (int h = 0; h < 8; h++) g_PB[h * 65536 + i * 256 + j] = phd[h];
}

// ============================================================================
extern "C" void kernel_launch(void* const* d_in, const int* in_sizes, int n_in,
                              void* d_out, int out_size) {
    (void)in_sizes; (void)n_in; (void)out_size;
    const float* x = (const float*)d_in[0];
    const float* pb = (const float*)d_in[1];
    const float* Wq_w = (const float*)d_in[2];
    const float* Wkv_w = (const float*)d_in[3];
    const float* Wout_w = (const float*)d_in[4];
    const float* bout_w = (const float*)d_in[5];
    const float* Wq_h = (const float*)d_in[6];
    const float* Wkv_h = (const float*)d_in[7];
    const float* Wout_h = (const float*)d_in[8];
    const float* bout_h = (const float*)d_in[9];
    const float* lng = (const float*)d_in[10];
    const float* lnb = (const float*)d_in[11];
    const float* Wp = (const float*)d_in[12];
    float* out = (float*)d_out;

    const int smw = (768 + 64) * XS * 2;   // Xh,Xl,Kh,Wh
    const int smp = (512 + 64) * XS * 2;   // Xh,Xl,Wh
    const int smd = (128 + 256) * XS * 2;  // Qh,Ql,Kh
    const int sma = (512 + 128) * XS * 2;  // Ph,Pl,Vh,Wh
    cudaFuncSetAttribute(k_width_mma, cudaFuncAttributeMaxDynamicSharedMemorySize, smw);
    cudaFuncSetAttribute(k_hproj_mma, cudaFuncAttributeMaxDynamicSharedMemorySize, smp);
    cudaFuncSetAttribute(k_hdots_mma, cudaFuncAttributeMaxDynamicSharedMemorySize, smd);
    cudaFuncSetAttribute(k_hav_mma, cudaFuncAttributeMaxDynamicSharedMemorySize, sma);

    k_init<<<16384, 256>>>(bout_w, bout_h, out);
    k_zero_dots<<<2048, 256>>>();
    k_hproj_mma<<<256, 512, smp>>>(x, Wq_h, Wkv_h);
    k_pair<<<8192, 256>>>(pb, lng, lnb, Wp);
    k_hdots_mma<<<dim3(4, 4, 8), 512, smd>>>();
    k_hsm2<<<256, 256>>>();
    k_hav_mma<<<dim3(256, 8), 512, sma>>>(Wout_h, out);
    k_width_mma<<<dim3(256, 8), 512, smw>>>(x, Wq_w, Wkv_w, Wout_w, out);
}